// round 14
// baseline (speedup 1.0000x reference)
#include <cuda_runtime.h>
#include <cuda_fp16.h>
#include <math.h>
#include <stdint.h>
#include <stddef.h>

// ---------------- problem dims (fixed) ----------------
#define BB   8
#define LL   2048
#define CIN  32
#define DMODEL 512
#define DFF  2048
#define NH   8
#define HD   64
#define NE   2
#define UU   24
#define MROWS (BB*LL)      // 16384

// converted-weight layout (fp16 element offsets)
#define QKV_PER_LAYER (1536*512)
#define WO_OFF   1572864
#define W1_OFF   2097152
#define W2_OFF   4194304
#define WTOT     6291456
#define WTOT_F4  1572864

// ---------------- scratch ----------------
__device__ float g_xln [MROWS*CIN];
__device__ float g_h   [(size_t)MROWS*DMODEL];
__device__ float g_M   [BB*NH*LL];
__device__ int   g_samp[LL*UU];
__device__ int   g_idxtop[BB*NH*UU];
__device__ float g_vmean[BB*NH*HD];
__device__ float g_upd [BB*NH*UU*HD];
__device__ float g_pe  [LL*DMODEL];
// split-K attention partials
__device__ float g_pacc[(size_t)BB*NH*8*UU*HD];
__device__ float g_pm  [BB*NH*8*UU];
__device__ float g_pl  [BB*NH*8*UU];
__device__ float g_pvs [BB*NH*8*HD];
__device__ __half g_qkvH[(size_t)MROWS*1536];
__device__ __half g_aH[(size_t)MROWS*DMODEL];
__device__ __half g_fH[(size_t)MROWS*DFF];
__device__ __half g_wbH[WTOT];

// ================= helpers =================
__device__ __forceinline__ uint32_t packhf(__half a, __half b) {
    __half2 t = __halves2half2(a, b);
    return *reinterpret_cast<uint32_t*>(&t);
}
__device__ __forceinline__ void mma16816(float* c, const uint32_t* a, const uint32_t* b) {
    asm volatile(
        "mma.sync.aligned.m16n8k16.row.col.f32.f16.f16.f32 "
        "{%0,%1,%2,%3}, {%4,%5,%6,%7}, {%8,%9}, {%0,%1,%2,%3};"
        : "+f"(c[0]), "+f"(c[1]), "+f"(c[2]), "+f"(c[3])
        : "r"(a[0]), "r"(a[1]), "r"(a[2]), "r"(a[3]), "r"(b[0]), "r"(b[1]));
}
__device__ __forceinline__ void ldsm4(uint32_t& r0, uint32_t& r1, uint32_t& r2, uint32_t& r3,
                                      uint32_t addr) {
    asm volatile("ldmatrix.sync.aligned.m8n8.x4.shared.b16 {%0,%1,%2,%3}, [%4];"
                 : "=r"(r0), "=r"(r1), "=r"(r2), "=r"(r3) : "r"(addr));
}
#define CP_ASYNC16(dst, src) \
    asm volatile("cp.async.ca.shared.global [%0], [%1], 16;" :: "r"(dst), "l"(src))
#define CP_COMMIT() asm volatile("cp.async.commit_group;" ::: "memory")
#define CP_WAIT1()  asm volatile("cp.async.wait_group 1;" ::: "memory")
#define CP_WAIT0()  asm volatile("cp.async.wait_group 0;" ::: "memory")

__device__ __forceinline__ void stage_tile(uint32_t dstBase, const __half* src,
                                           int K, int k0, int tid) {
    int row = tid >> 2, c = tid & 3;
    #pragma unroll
    for (int i = 0; i < 2; i++) {
        int r = row + 64 * i;
        uint32_t doff = (uint32_t)(r * 64 + ((c ^ ((r >> 1) & 3)) << 4));
        CP_ASYNC16(dstBase + doff, src + (size_t)r * K + k0 + c * 8);
    }
}

// ================= 3-stage pipelined single-pass fp16 tensor GEMM =================
template<int RELU, int RES, int OUT, int SEGB>
__global__ __launch_bounds__(256, 2)
void tgemm_kernel(const __half* __restrict__ aH, const __half* __restrict__ bH,
                  const float* __restrict__ b0, const float* __restrict__ b1,
                  const float* __restrict__ b2,
                  const float* __restrict__ res, float* __restrict__ C,
                  __half* __restrict__ outH,
                  int M, int N, int K) {
    extern __shared__ char smem[];
    uint32_t sb = (uint32_t)__cvta_generic_to_shared(smem);

    int tid = threadIdx.x;
    int wid = tid >> 5, lane = tid & 31;
    int warpM = wid >> 2, warpN = wid & 3;
    int bn = blockIdx.x, bm = blockIdx.y;

    const __half* Ah = aH + (size_t)(bm * 128) * K;
    const __half* Bh = bH + (size_t)(bn * 128) * K;

    float acc[4][4][4];
    #pragma unroll
    for (int mt = 0; mt < 4; mt++)
        #pragma unroll
        for (int nt = 0; nt < 4; nt++)
            #pragma unroll
            for (int e = 0; e < 4; e++) acc[mt][nt][e] = 0.f;

    int nchunks = K >> 5;
    #pragma unroll
    for (int s = 0; s < 2; s++) {
        uint32_t sd = sb + s * 16384;
        stage_tile(sd,        Ah, K, s * 32, tid);
        stage_tile(sd + 8192, Bh, K, s * 32, tid);
        CP_COMMIT();
    }

    int slot = 0, nslot = 2;
    for (int c = 0; c < nchunks; c++) {
        if (c + 1 < nchunks) CP_WAIT1(); else CP_WAIT0();
        __syncthreads();
        if (c + 2 < nchunks) {
            uint32_t sd = sb + nslot * 16384;
            int k0 = (c + 2) * 32;
            stage_tile(sd,        Ah, K, k0, tid);
            stage_tile(sd + 8192, Bh, K, k0, tid);
            CP_COMMIT();
        }

        uint32_t st = sb + slot * 16384;
        #pragma unroll
        for (int ks = 0; ks < 2; ks++) {
            int cidx = ks * 2 + (lane >> 4);
            int arow = warpM * 64 + (lane & 15);
            int brow = warpN * 32 + (lane & 15);
            uint32_t a4[4][4];
            uint32_t b4[4][2];
            #pragma unroll
            for (int mt = 0; mt < 4; mt++) {
                int row = arow + mt * 16;
                ldsm4(a4[mt][0], a4[mt][1], a4[mt][2], a4[mt][3],
                      st + row * 64 + ((cidx ^ ((row >> 1) & 3)) << 4));
            }
            #pragma unroll
            for (int p = 0; p < 2; p++) {
                int row = brow + p * 16;
                uint32_t off = (uint32_t)(row * 64 + ((cidx ^ ((row >> 1) & 3)) << 4));
                uint32_t r0, r1, r2, r3;
                ldsm4(r0, r1, r2, r3, st + 8192 + off);
                b4[p*2][0] = r0; b4[p*2+1][0] = r1;
                b4[p*2][1] = r2; b4[p*2+1][1] = r3;
            }
            #pragma unroll
            for (int mt = 0; mt < 4; mt++)
                #pragma unroll
                for (int nt = 0; nt < 4; nt++)
                    mma16816(acc[mt][nt], a4[mt], b4[nt]);
        }
        slot = (slot == 2) ? 0 : slot + 1;
        nslot = (nslot == 2) ? 0 : nslot + 1;
    }

    #pragma unroll
    for (int mt = 0; mt < 4; mt++) {
        int r0 = bm * 128 + warpM * 64 + mt * 16 + (lane >> 2);
        #pragma unroll
        for (int nt = 0; nt < 4; nt++) {
            int cc = bn * 128 + warpN * 32 + nt * 8 + (lane & 3) * 2;
            const float* bp;
            int cb;
            if (SEGB) {
                int seg = cc >> 9;
                bp = (seg == 0) ? b0 : ((seg == 1) ? b1 : b2);
                cb = cc & 511;
            } else { bp = b0; cb = cc; }
            float2 bi = *(const float2*)(bp + cb);
            float2 o0 = make_float2(acc[mt][nt][0] + bi.x, acc[mt][nt][1] + bi.y);
            float2 o1 = make_float2(acc[mt][nt][2] + bi.x, acc[mt][nt][3] + bi.y);
            size_t g0 = (size_t)r0 * N + cc;
            size_t g1 = (size_t)(r0 + 8) * N + cc;
            if (RES) {
                float2 q0 = *(const float2*)(res + g0);
                float2 q1 = *(const float2*)(res + g1);
                o0.x += q0.x; o0.y += q0.y; o1.x += q1.x; o1.y += q1.y;
            }
            if (RELU) {
                o0.x = fmaxf(o0.x, 0.f); o0.y = fmaxf(o0.y, 0.f);
                o1.x = fmaxf(o1.x, 0.f); o1.y = fmaxf(o1.y, 0.f);
            }
            if (OUT == 0) {
                *(float2*)(C + g0) = o0;
                *(float2*)(C + g1) = o1;
            } else {
                *(uint32_t*)(outH + g0) = packhf(__float2half_rn(o0.x), __float2half_rn(o0.y));
                *(uint32_t*)(outH + g1) = packhf(__float2half_rn(o1.x), __float2half_rn(o1.y));
            }
        }
    }
}

// ---------------- all-weight fp16 conversion (once; QKV|WO|W1|W2) ----------------
__global__ void wconv_kernel(const float4* __restrict__ Wq, const float4* __restrict__ Wk,
                             const float4* __restrict__ Wv, const float4* __restrict__ Wo,
                             const float4* __restrict__ W1, const float4* __restrict__ W2) {
    int j = blockIdx.x * 256 + threadIdx.x;
    if (j >= WTOT_F4) return;
    const float4* src;
    if (j < 393216) {
        int layer = j / 196608;
        int r = j - layer * 196608;
        int seg = r >> 16, off = r & 65535;
        const float4* base = (seg == 0) ? Wq : ((seg == 1) ? Wk : Wv);
        src = base + layer * 65536 + off;
    } else if (j < 524288) {
        src = Wo + (j - 393216);
    } else if (j < 1048576) {
        src = W1 + (j - 524288);
    } else {
        src = W2 + (j - 1048576);
    }
    float4 f = *src;
    ((uint2*)g_wbH)[j] = make_uint2(
        packhf(__float2half_rn(f.x), __float2half_rn(f.y)),
        packhf(__float2half_rn(f.z), __float2half_rn(f.w)));
}

// ---------------- positional-embedding table (once) ----------------
__global__ void pe_kernel() {
    int i2 = blockIdx.x;
    double dv = exp(-(double)(2 * i2) * (9.210340371976184 / 512.0));
    const double TWO_PI = 6.283185307179586;
    const double INV2PI = 0.15915494309189535;
    for (int l = threadIdx.x; l < LL; l += 256) {
        double arg = (double)l * dv;
        double qd = rint(arg * INV2PI);
        double r = fma(-qd, TWO_PI, arg);
        float rf = (float)r;
        g_pe[l * DMODEL + 2 * i2]     = sinf(rf);
        g_pe[l * DMODEL + 2 * i2 + 1] = cosf(rf);
    }
}

// ---------------- threefry2x32 (JAX partitionable) ----------------
__device__ __forceinline__ void tf2x32(uint32_t k0, uint32_t k1,
                                       uint32_t x0, uint32_t x1,
                                       uint32_t& o0, uint32_t& o1) {
    uint32_t ks2 = k0 ^ k1 ^ 0x1BD11BDAu;
    uint32_t v0 = x0 + k0, v1 = x1 + k1;
#define TF_RND(r) { v0 += v1; v1 = (v1 << (r)) | (v1 >> (32 - (r))); v1 ^= v0; }
    TF_RND(13) TF_RND(15) TF_RND(26) TF_RND(6)   v0 += k1;  v1 += ks2 + 1u;
    TF_RND(17) TF_RND(29) TF_RND(16) TF_RND(24)  v0 += ks2; v1 += k0 + 2u;
    TF_RND(13) TF_RND(15) TF_RND(26) TF_RND(6)   v0 += k0;  v1 += k1 + 3u;
    TF_RND(17) TF_RND(29) TF_RND(16) TF_RND(24)  v0 += k1;  v1 += ks2 + 4u;
    TF_RND(13) TF_RND(15) TF_RND(26) TF_RND(6)   v0 += ks2; v1 += k0 + 5u;
#undef TF_RND
    o0 = v0; o1 = v1;
}

__global__ void sample_kernel(int layer) {
    int j = blockIdx.x * blockDim.x + threadIdx.x;
    if (j >= LL * UU) return;
    uint32_t a0, a1;
    tf2x32(0u, 42u, 0u, (uint32_t)layer, a0, a1);
    uint32_t k2a, k2b;
    tf2x32(a0, a1, 0u, 1u, k2a, k2b);
    uint32_t o0, o1;
    tf2x32(k2a, k2b, 0u, (uint32_t)j, o0, o1);
    g_samp[j] = (int)((o0 ^ o1) & 2047u);
}

// ---------------- input layernorm over C_IN=32 ----------------
__global__ void ln32_kernel(const float* __restrict__ x,
                            const float* __restrict__ g, const float* __restrict__ b) {
    int row  = blockIdx.x * 8 + (threadIdx.x >> 5);
    int lane = threadIdx.x & 31;
    float v = x[(size_t)row * CIN + lane];
    float s = v;
    #pragma unroll
    for (int o = 16; o; o >>= 1) s += __shfl_xor_sync(~0u, s, o);
    float m = s * (1.f / 32.f);
    float d = v - m;
    float ss = d * d;
    #pragma unroll
    for (int o = 16; o; o >>= 1) ss += __shfl_xor_sync(~0u, ss, o);
    float r = rsqrtf(ss * (1.f / 32.f) + 1e-5f);
    g_xln[(size_t)row * CIN + lane] = d * r * g[lane] + b[lane];
}

// ---------------- token conv + pe table + time proj ----------------
__global__ void embed_kernel(const float* __restrict__ tfeat,
                             const float* __restrict__ Wtok,
                             const float* __restrict__ Wtime,
                             const float* __restrict__ btime) {
    int bl = blockIdx.x;
    int l = bl & (LL - 1);
    int b = bl >> 11;
    __shared__ float xs[96];
    __shared__ float tf[4];
    int tid = threadIdx.x; // 128
    if (tid < 96) {
        int w = tid / 32, c = tid % 32;
        int lsrc = (l - 1 + w + LL) & (LL - 1);
        xs[tid] = g_xln[((size_t)b * LL + lsrc) * CIN + c];
    }
    if (tid < 4) tf[tid] = tfeat[((size_t)b * LL + l) * 4 + tid];
    __syncthreads();
    for (int m = tid; m < DMODEL; m += 128) {
        float acc = btime[m];
        #pragma unroll 8
        for (int wc = 0; wc < 96; wc++) acc += xs[wc] * Wtok[wc * DMODEL + m];
        #pragma unroll
        for (int t = 0; t < 4; t++) acc += tf[t] * Wtime[m * 4 + t];
        float v = acc + g_pe[l * DMODEL + m];
        size_t idx = ((size_t)b * LL + l) * DMODEL + m;
        g_h[idx] = v;
        g_aH[idx] = __float2half_rn(v);
    }
}

// ---------------- M scores (fp16 QKV) ----------------
__global__ void mscore_kernel() {
    int wid  = (blockIdx.x * blockDim.x + threadIdx.x) >> 5;
    int lane = threadIdx.x & 31;
    if (wid >= BB * NH * LL) return;
    int l = wid & (LL - 1);
    int h = (wid >> 11) & (NH - 1);
    int b = wid >> 14;
    const __half* qr = g_qkvH + ((size_t)b * LL + l) * 1536 + h * 64;
    float2 qf = __half22float2(*(const __half2*)(qr + lane * 2));
    float mx = -INFINITY, sm = 0.f;
    #pragma unroll 4
    for (int s = 0; s < UU; s++) {
        int ks = g_samp[l * UU + s];
        const __half* kr = g_qkvH + ((size_t)b * LL + ks) * 1536 + 512 + h * 64;
        float2 kf = __half22float2(*(const __half2*)(kr + lane * 2));
        float v = qf.x * kf.x + qf.y * kf.y;
        #pragma unroll
        for (int o = 16; o; o >>= 1) v += __shfl_xor_sync(~0u, v, o);
        mx = fmaxf(mx, v);
        sm += v;
    }
    if (lane == 0)
        g_M[((size_t)(b * NH + h)) * LL + l] = mx - sm * (1.0f / (float)LL);
}

// ---------------- top-24 per (b,h), JAX tie semantics ----------------
__global__ void topk_kernel() {
    int bh = blockIdx.x;
    int tid = threadIdx.x;   // 256
    __shared__ float sv[LL];
    __shared__ float rv[256];
    __shared__ int   ri[256];
    for (int i = tid; i < LL; i += 256) sv[i] = g_M[(size_t)bh * LL + i];
    __syncthreads();
    for (int t = 0; t < UU; t++) {
        float bvv = -INFINITY; int bi = LL;
        for (int i = tid; i < LL; i += 256) {
            float v = sv[i];
            if (v > bvv || (v == bvv && i < bi)) { bvv = v; bi = i; }
        }
        rv[tid] = bvv; ri[tid] = bi;
        __syncthreads();
        for (int s = 128; s > 0; s >>= 1) {
            if (tid < s) {
                float v2 = rv[tid + s]; int i2 = ri[tid + s];
                if (v2 > rv[tid] || (v2 == rv[tid] && i2 < ri[tid])) { rv[tid] = v2; ri[tid] = i2; }
            }
            __syncthreads();
        }
        if (tid == 0) { g_idxtop[bh * UU + t] = ri[0]; sv[ri[0]] = -INFINITY; }
        __syncthreads();
    }
}

// ---------------- split-K attention phase 1 (fp16 QKV) ----------------
__global__ __launch_bounds__(256)
void attnpart_kernel() {    // grid (64, 8), 256 threads
    int bh = blockIdx.x, kt = blockIdx.y;
    int h = bh & 7, b = bh >> 3;
    int tid = threadIdx.x;
    int wid = tid >> 5, lane = tid & 31;
    int d = tid & 63, part = tid >> 6;
    size_t bL = (size_t)b * LL;

    __shared__ float qs[UU * 64];
    __shared__ float sc[UU][257];
    __shared__ float mt_[UU], lt_[UU];
    __shared__ float svs[4][64];

    for (int i = tid; i < UU * 64; i += 256) {
        int u = i >> 6, dd = i & 63;
        qs[i] = __half2float(g_qkvH[(bL + g_idxtop[bh * UU + u]) * 1536 + h * 64 + dd]);
    }
    __syncthreads();

    // K row for this thread's key -> fp32 registers
    int k = kt * 256 + tid;
    float krf[64];
    {
        const uint4* kp = (const uint4*)(g_qkvH + (bL + k) * 1536 + 512 + h * 64);
        #pragma unroll
        for (int i = 0; i < 8; i++) {
            uint4 w = kp[i];
            const __half2* hp = (const __half2*)&w;
            #pragma unroll
            for (int j = 0; j < 4; j++) {
                float2 f = __half22float2(hp[j]);
                krf[i * 8 + j * 2]     = f.x;
                krf[i * 8 + j * 2 + 1] = f.y;
            }
        }
    }
    #pragma unroll 4
    for (int u = 0; u < UU; u++) {
        const float* qp = qs + u * 64;
        float s = 0.f;
        #pragma unroll
        for (int i = 0; i < 64; i++) s += qp[i] * krf[i];
        sc[u][tid] = s * 0.125f;
    }
    __syncthreads();

    #pragma unroll
    for (int j = 0; j < 3; j++) {
        int u = wid * 3 + j;
        float tm = -INFINITY;
        #pragma unroll
        for (int i = 0; i < 8; i++) tm = fmaxf(tm, sc[u][lane + 32 * i]);
        #pragma unroll
        for (int o = 16; o; o >>= 1) tm = fmaxf(tm, __shfl_xor_sync(~0u, tm, o));
        if (lane == 0) mt_[u] = tm;
    }
    __syncthreads();

    #pragma unroll 4
    for (int u = 0; u < UU; u++)
        sc[u][tid] = expf(sc[u][tid] - mt_[u]);
    __syncthreads();

    #pragma unroll
    for (int j = 0; j < 3; j++) {
        int u = wid * 3 + j;
        float ts = 0.f;
        #pragma unroll
        for (int i = 0; i < 8; i++) ts += sc[u][lane + 32 * i];
        #pragma unroll
        for (int o = 16; o; o >>= 1) ts += __shfl_xor_sync(~0u, ts, o);
        if (lane == 0) lt_[u] = ts;
    }

    float acc[UU];
    #pragma unroll
    for (int u = 0; u < UU; u++) acc[u] = 0.f;
    float vsum = 0.f;
    for (int kk = part; kk < 256; kk += 4) {
        float v = __half2float(g_qkvH[(bL + kt * 256 + kk) * 1536 + 1024 + h * 64 + d]);
        vsum += v;
        #pragma unroll
        for (int u = 0; u < UU; u++) acc[u] += sc[u][kk] * v;
    }
    __syncthreads();

    #pragma unroll 4
    for (int u = 0; u < UU; u++) sc[u][part * 64 + d] = acc[u];
    svs[part][d] = vsum;
    __syncthreads();

    #pragma unroll
    for (int uu = 0; uu < 6; uu++) {
        int u = uu * 4 + part;
        float tot = sc[u][d] + sc[u][64 + d] + sc[u][128 + d] + sc[u][192 + d];
        g_pacc[(((size_t)bh * 8 + kt) * UU + u) * HD + d] = tot;
    }
    if (tid < UU) {
        g_pm[(bh * 8 + kt) * UU + tid] = mt_[tid];
        g_pl[(bh * 8 + kt) * UU + tid] = lt_[tid];
    }
    if (tid < 64)
        g_pvs[(bh * 8 + kt) * HD + tid] =
            svs[0][tid] + svs[1][tid] + svs[2][tid] + svs[3][tid];
}

// ---------------- split-K attention phase 2: deterministic combine ----------------
__global__ void attncomb_kernel() {   // grid 64, 256 threads
    int bh = blockIdx.x;
    int tid = threadIdx.x;
    int d = tid & 63, ug = tid >> 6;
    #pragma unroll
    for (int uu = 0; uu < 6; uu++) {
        int u = uu * 4 + ug;
        float m = -INFINITY;
        #pragma unroll
        for (int kt = 0; kt < 8; kt++)
            m = fmaxf(m, g_pm[(bh * 8 + kt) * UU + u]);
        float denom = 0.f, numer = 0.f;
        #pragma unroll
        for (int kt = 0; kt < 8; kt++) {
            float e = expf(g_pm[(bh * 8 + kt) * UU + u] - m);
            denom += g_pl[(bh * 8 + kt) * UU + u] * e;
            numer += g_pacc[(((size_t)bh * 8 + kt) * UU + u) * HD + d] * e;
        }
        g_upd[((size_t)bh * UU + u) * HD + d] = numer / denom;
    }
    if (tid < 64) {
        float s = 0.f;
        #pragma unroll
        for (int kt = 0; kt < 8; kt++) s += g_pvs[(bh * 8 + kt) * HD + tid];
        g_vmean[bh * HD + tid] = s * (1.0f / (float)LL);
    }
}

// ---------------- broadcast vmean into fp16 attn buffer ----------------
__global__ void fill_kernel() {
    size_t i = (size_t)blockIdx.x * 256 + threadIdx.x;
    size_t e = i * 2;
    int d = (int)(e & 63);
    int h = (int)((e >> 6) & 7);
    int b = (int)(e >> 20);
    float v0 = g_vmean[(b * NH + h) * HD + d];
    float v1 = g_vmean[(b * NH + h) * HD + d + 1];
    *(uint32_t*)(g_aH + e) = packhf(__float2half_rn(v0), __float2half_rn(v1));
}

// ---------------- scatter updated rows (fp16) ----------------
__global__ void scatter_kernel() {
    int bid = blockIdx.x;
    int u = bid % UU;
    int bh = bid / UU;
    int h = bh & (NH - 1), b = bh >> 3;
    int qi = g_idxtop[bh * UU + u];
    float v = g_upd[(size_t)bid * HD + threadIdx.x];
    size_t idx = (((size_t)b * LL + qi) * NH + h) * HD + threadIdx.x;
    g_aH[idx] = __float2half_rn(v);
}

// ---------------- layernorm over 512 (optionally emits fp16) ----------------
__global__ void ln512_kernel(const float* __restrict__ in, float* __restrict__ out,
                             const float* __restrict__ g, const float* __restrict__ b,
                             size_t strideIn, size_t strideOut,
                             __half* __restrict__ hOut) {
    int row = blockIdx.x;
    int tid = threadIdx.x;  // 128
    const float* x = in + (size_t)row * strideIn;
    float4 v = *(const float4*)(x + tid * 4);
    float s  = v.x + v.y + v.z + v.w;
    float ss = v.x*v.x + v.y*v.y + v.z*v.z + v.w*v.w;
    __shared__ float rs[4], rss[4];
    #pragma unroll
    for (int o = 16; o; o >>= 1) {
        s  += __shfl_xor_sync(~0u, s, o);
        ss += __shfl_xor_sync(~0u, ss, o);
    }
    int w = tid >> 5, lane = tid & 31;
    if (lane == 0) { rs[w] = s; rss[w] = ss; }
    __syncthreads();
    s  = rs[0] + rs[1] + rs[2] + rs[3];
    ss = rss[0] + rss[1] + rss[2] + rss[3];
    float m = s * (1.f / 512.f);
    float var = ss * (1.f / 512.f) - m * m;
    float r = rsqrtf(var + 1e-5f);
    float4 gg = *(const float4*)(g + tid * 4);
    float4 bb = *(const float4*)(b + tid * 4);
    float4 o4;
    o4.x = (v.x - m) * r * gg.x + bb.x;
    o4.y = (v.y - m) * r * gg.y + bb.y;
    o4.z = (v.z - m) * r * gg.z + bb.z;
    o4.w = (v.w - m) * r * gg.w + bb.w;
    *(float4*)(out + (size_t)row * strideOut + tid * 4) = o4;
    if (hOut) {
        size_t e = (size_t)row * DMODEL + tid * 4;
        *(uint2*)(hOut + e) = make_uint2(
            packhf(__float2half_rn(o4.x), __float2half_rn(o4.y)),
            packhf(__float2half_rn(o4.z), __float2half_rn(o4.w)));
    }
}

// ---------------- tail: layer-2 post-attention for the LAST row of each batch -----
__global__ __launch_bounds__(512)
void tail_kernel(const float* __restrict__ Wo, const float* __restrict__ bo,
                 const float* __restrict__ W1, const float* __restrict__ b1,
                 const float* __restrict__ W2, const float* __restrict__ b2,
                 const float* __restrict__ g1v, const float* __restrict__ be1v,
                 const float* __restrict__ g2v, const float* __restrict__ be2v,
                 const float* __restrict__ genc, const float* __restrict__ benc,
                 const float* __restrict__ Wpre, const float* __restrict__ bpre,
                 const float* __restrict__ Wfc,  const float* __restrict__ bfc,
                 float* __restrict__ out) {
    int b = blockIdx.x;           // 8
    int tid = threadIdx.x;        // 512
    int wid = tid >> 5, lane = tid & 31;
    __shared__ float av[512];
    __shared__ float hA[512];
    __shared__ float hid[2048];
    __shared__ float rs[16], rss[16];

    {
        int h = tid >> 6, d = tid & 63;
        float v = g_vmean[(b * NH + h) * HD + d];
        #pragma unroll 4
        for (int u = 0; u < UU; u++)
            if (g_idxtop[(b * NH + h) * UU + u] == LL - 1)
                v = g_upd[((size_t)(b * NH + h) * UU + u) * HD + d];
        av[tid] = v;
    }
    __syncthreads();

    float t = bo[tid];
    {
        const float4* wr = (const float4*)(Wo + (size_t)tid * 512);
        const float4* ar = (const float4*)av;
        #pragma unroll 8
        for (int k = 0; k < 128; k++) {
            float4 w4 = wr[k], a4 = ar[k];
            t += a4.x * w4.x + a4.y * w4.y + a4.z * w4.z + a4.w * w4.w;
        }
        t += g_h[((size_t)b * LL + (LL - 1)) * DMODEL + tid];
    }

    {
        float s = t, ss = t * t;
        #pragma unroll
        for (int o = 16; o; o >>= 1) {
            s  += __shfl_xor_sync(~0u, s, o);
            ss += __shfl_xor_sync(~0u, ss, o);
        }
        if (lane == 0) { rs[wid] = s; rss[wid] = ss; }
        __syncthreads();
        float S = 0.f, SS = 0.f;
        #pragma unroll
        for (int w = 0; w < 16; w++) { S += rs[w]; SS += rss[w]; }
        float m = S * (1.f / 512.f);
        float r = rsqrtf(SS * (1.f / 512.f) - m * m + 1e-5f);
        hA[tid] = (t - m) * r * g1v[tid] + be1v[tid];
        __syncthreads();
    }

    #pragma unroll
    for (int jj = 0; jj < 4; jj++) {
        int j = tid + jj * 512;
        float acc = b1[j];
        const float4* wr = (const float4*)(W1 + (size_t)j * 512);
        const float4* ar = (const float4*)hA;
        #pragma unroll 8
        for (int k = 0; k < 128; k++) {
            float4 w4 = wr[k], a4 = ar[k];
            acc += a4.x * w4.x + a4.y * w4.y + a4.z * w4.z + a4.w * w4.w;
        }
        hid[j] = fmaxf(acc, 0.f);
    }
    __syncthreads();

    float t2;
    {
        float acc = b2[tid];
        const float4* wr = (const float4*)(W2 + (size_t)tid * 2048);
        const float4* ar = (const float4*)hid;
        #pragma unroll 8
        for (int k = 0; k < 512; k++) {
            float4 w4 = wr[k], a4 = ar[k];
            acc += a4.x * w4.x + a4.y * w4.y + a4.z * w4.z + a4.w * w4.w;
        }
        t2 = hA[tid] + acc;
    }
    __syncthreads();

    {
        float s = t2, ss = t2 * t2;
        #pragma unroll
        for (int o = 16; o; o >>= 1) {
            s  += __shfl_xor_sync(~0u, s, o);
            ss += __shfl_xor_sync(~0u, ss, o);
        }
        if (lane == 0) { rs[wid] = s; rss[wid] = ss; }
        __syncthreads();
        float S = 0.f, SS = 0.f;
        #pragma unroll
        for (int w = 0; w < 16; w++) { S += rs[w]; SS += rss[w]; }
        float m = S * (1.f / 512.f);
        float r = rsqrtf(SS * (1.f / 512.f) - m * m + 1e-5f);
        float hB = (t2 - m) * r * g2v[tid] + be2v[tid];
        __syncthreads();

        s = hB; ss = hB * hB;
        #pragma unroll
        for (int o = 16; o; o >>= 1) {
            s  += __shfl_xor_sync(~0u, s, o);
            ss += __shfl_xor_sync(~0u, ss, o);
        }
        if (lane == 0) { rs[wid] = s; rss[wid] = ss; }
        __syncthreads();
        S = 0.f; SS = 0.f;
        #pragma unroll
        for (int w = 0; w < 16; w++) { S += rs[w]; SS += rss[w]; }
        m = S * (1.f / 512.f);
        r = rsqrtf(SS * (1.f / 512.f) - m * m + 1e-5f);
        av[tid] = (hB - m) * r * genc[tid] + benc[tid];
        __syncthreads();
    }

    float contrib = 0.f;
    if (tid < 256) {
        float acc = bpre[tid];
        const float4* wr = (const float4*)(Wpre + (size_t)tid * 512);
        const float4* ar = (const float4*)av;
        #pragma unroll 8
        for (int k = 0; k < 128; k++) {
            float4 w4 = wr[k], a4 = ar[k];
            acc += a4.x * w4.x + a4.y * w4.y + a4.z * w4.z + a4.w * w4.w;
        }
        contrib = fmaxf(acc, 0.f) * Wfc[tid];
    }
    {
        float s = contrib;
        #pragma unroll
        for (int o = 16; o; o >>= 1) s += __shfl_xor_sync(~0u, s, o);
        if (lane == 0) rs[wid] = s;
        __syncthreads();
        if (tid == 0) {
            float S = 0.f;
            #pragma unroll
            for (int w = 0; w < 16; w++) S += rs[w];
            out[b] = S + bfc[0];
        }
    }
}

// ---------------- host orchestration ----------------
#define SMEM_GEMM 49152

extern "C" void kernel_launch(void* const* d_in, const int* in_sizes, int n_in,
                              void* d_out, int out_size) {
    const float* x      = (const float*)d_in[0];
    const float* tfeat  = (const float*)d_in[1];
    const float* g_in   = (const float*)d_in[2];
    const float* b_in   = (const float*)d_in[3];
    const float* W_tok  = (const float*)d_in[4];
    const float* W_time = (const float*)d_in[5];
    const float* b_time = (const float*)d_in[6];
    const float* Wq     = (const float*)d_in[7];
    const float* bq     = (const float*)d_in[8];
    const float* Wk     = (const float*)d_in[9];
    const float* bk     = (const float*)d_in[10];
    const float* Wv     = (const float*)d_in[11];
    const float* bv     = (const float*)d_in[12];
    const float* Wo     = (const float*)d_in[13];
    const float* bo     = (const float*)d_in[14];
    const float* W1     = (const float*)d_in[15];
    const float* b1     = (const float*)d_in[16];
    const float* W2     = (const float*)d_in[17];
    const float* b2     = (const float*)d_in[18];
    const float* g1     = (const float*)d_in[19];
    const float* be1    = (const float*)d_in[20];
    const float* g2     = (const float*)d_in[21];
    const float* be2    = (const float*)d_in[22];
    const float* g_enc  = (const float*)d_in[23];
    const float* b_enc  = (const float*)d_in[24];
    const float* W_pre  = (const float*)d_in[25];
    const float* b_pre  = (const float*)d_in[26];
    const float* W_fc   = (const float*)d_in[27];
    const float* b_fc   = (const float*)d_in[28];

    float *h;
    __half *aH, *fH, *wbH, *qkvH;
    cudaGetSymbolAddress((void**)&h,    g_h);
    cudaGetSymbolAddress((void**)&aH,   g_aH);
    cudaGetSymbolAddress((void**)&fH,   g_fH);
    cudaGetSymbolAddress((void**)&wbH,  g_wbH);
    cudaGetSymbolAddress((void**)&qkvH, g_qkvH);

    cudaFuncSetAttribute(tgemm_kernel<0,0,1,1>, cudaFuncAttributeMaxDynamicSharedMemorySize, SMEM_GEMM);
    cudaFuncSetAttribute(tgemm_kernel<1,0,1,0>, cudaFuncAttributeMaxDynamicSharedMemorySize, SMEM_GEMM);
    cudaFuncSetAttribute(tgemm_kernel<0,1,0,0>, cudaFuncAttributeMaxDynamicSharedMemorySize, SMEM_GEMM);

    pe_kernel<<<256, 256>>>();
    ln32_kernel<<<MROWS / 8, 256>>>(x, g_in, b_in);
    embed_kernel<<<MROWS, 128>>>(tfeat, W_tok, W_time, b_time);
    wconv_kernel<<<WTOT_F4 / 256, 256>>>((const float4*)Wq, (const float4*)Wk,
                                         (const float4*)Wv, (const float4*)Wo,
                                         (const float4*)W1, (const float4*)W2);

    dim3 gQKV(1536 / 128, MROWS / 128);
    dim3 gO(DMODEL / 128, MROWS / 128);
    dim3 gF1(DFF / 128,  MROWS / 128);
    dim3 gF2(DMODEL / 128, MROWS / 128);

    for (int i = 0; i < NE; i++) {
        size_t bOff  = (size_t)i * DMODEL;
        size_t b1Off = (size_t)i * DFF;
        size_t qkvW  = (size_t)i * QKV_PER_LAYER;
        size_t woW   = WO_OFF + (size_t)i * DMODEL * DMODEL;
        size_t w1W   = W1_OFF + (size_t)i * DFF * DMODEL;
        size_t w2W   = W2_OFF + (size_t)i * DFF * DMODEL;

        sample_kernel<<<(LL * UU + 255) / 256, 256>>>(i);

        tgemm_kernel<0,0,1,1><<<gQKV, 256, SMEM_GEMM>>>(
            aH, wbH + qkvW,
            bq + bOff, bk + bOff, bv + bOff, nullptr, nullptr, qkvH,
            MROWS, 1536, DMODEL);

        mscore_kernel<<<(BB * NH * LL * 32) / 256, 256>>>();
        topk_kernel<<<BB * NH, 256>>>();
        attnpart_kernel<<<dim3(BB * NH, 8), 256>>>();
        attncomb_kernel<<<BB * NH, 256>>>();

        if (i == 0) {
            fill_kernel<<<(MROWS * DMODEL / 2) / 256, 256>>>();
            scatter_kernel<<<BB * NH * UU, HD>>>();

            tgemm_kernel<0,1,0,0><<<gO, 256, SMEM_GEMM>>>(
                aH, wbH + woW,
                bo + bOff, nullptr, nullptr, h, h, nullptr,
                MROWS, DMODEL, DMODEL);
            ln512_kernel<<<MROWS, 128>>>(h, h, g1 + bOff, be1 + bOff, DMODEL, DMODEL, aH);

            tgemm_kernel<1,0,1,0><<<gF1, 256, SMEM_GEMM>>>(
                aH, wbH + w1W,
                b1 + b1Off, nullptr, nullptr, nullptr, nullptr, fH,
                MROWS, DFF, DMODEL);
            tgemm_kernel<0,1,0,0><<<gF2, 256, SMEM_GEMM>>>(
                fH, wbH + w2W,
                b2 + bOff, nullptr, nullptr, h, h, nullptr,
                MROWS, DMODEL, DFF);
            ln512_kernel<<<MROWS, 128>>>(h, h, g2 + bOff, be2 + bOff, DMODEL, DMODEL, aH);
        } else {
            // layer 2: only row L-1 per batch reaches the output -> fp32 tail
            tail_kernel<<<BB, 512>>>(
                Wo + (size_t)i * DMODEL * DMODEL, bo + bOff,
                W1 + (size_t)i * DFF * DMODEL, b1 + b1Off,
                W2 + (size_t)i * DMODEL * DFF, b2 + bOff,
                g1 + bOff, be1 + bOff, g2 + bOff, be2 + bOff,
                g_enc, b_enc, W_pre, b_pre, W_fc, b_fc, (float*)d_out);
        }
    }
}

// round 16
// speedup vs baseline: 1.5254x; 1.5254x over previous
#include <cuda_runtime.h>
#include <cuda_fp16.h>
#include <math.h>
#include <stdint.h>
#include <stddef.h>

// ---------------- problem dims (fixed) ----------------
#define BB   8
#define LL   2048
#define CIN  32
#define DMODEL 512
#define DFF  2048
#define NH   8
#define HD   64
#define NE   2
#define UU   24
#define MROWS (BB*LL)      // 16384

// converted-weight layout (fp16 element offsets)
#define QKV_PER_LAYER (1536*512)
#define WO_OFF   1572864
#define W1_OFF   2097152
#define W2_OFF   4194304
#define WTOT     6291456
#define WTOT_F4  1572864

// ---------------- scratch ----------------
__device__ float g_xln [MROWS*CIN];
__device__ float g_h   [(size_t)MROWS*DMODEL];
__device__ float g_qkv [(size_t)MROWS*1536];
__device__ float g_M   [BB*NH*LL];
__device__ int   g_samp[LL*UU];
__device__ int   g_idxtop[BB*NH*UU];
__device__ float g_vmean[BB*NH*HD];
__device__ float g_upd [BB*NH*UU*HD];
__device__ float g_pe  [LL*DMODEL];
// split-K attention partials
__device__ float g_pacc[(size_t)BB*NH*8*UU*HD];
__device__ float g_pm  [BB*NH*8*UU];
__device__ float g_pl  [BB*NH*8*UU];
__device__ float g_pvs [BB*NH*8*HD];
__device__ __half g_aH[(size_t)MROWS*DMODEL];
__device__ __half g_fH[(size_t)MROWS*DFF];
__device__ __half g_wbH[WTOT];

// ================= helpers =================
__device__ __forceinline__ uint32_t packhf(__half a, __half b) {
    __half2 t = __halves2half2(a, b);
    return *reinterpret_cast<uint32_t*>(&t);
}
__device__ __forceinline__ void mma16816(float* c, const uint32_t* a, const uint32_t* b) {
    asm volatile(
        "mma.sync.aligned.m16n8k16.row.col.f32.f16.f16.f32 "
        "{%0,%1,%2,%3}, {%4,%5,%6,%7}, {%8,%9}, {%0,%1,%2,%3};"
        : "+f"(c[0]), "+f"(c[1]), "+f"(c[2]), "+f"(c[3])
        : "r"(a[0]), "r"(a[1]), "r"(a[2]), "r"(a[3]), "r"(b[0]), "r"(b[1]));
}
__device__ __forceinline__ void ldsm4(uint32_t& r0, uint32_t& r1, uint32_t& r2, uint32_t& r3,
                                      uint32_t addr) {
    asm volatile("ldmatrix.sync.aligned.m8n8.x4.shared.b16 {%0,%1,%2,%3}, [%4];"
                 : "=r"(r0), "=r"(r1), "=r"(r2), "=r"(r3) : "r"(addr));
}
#define CP_ASYNC16(dst, src) \
    asm volatile("cp.async.ca.shared.global [%0], [%1], 16;" :: "r"(dst), "l"(src))
#define CP_COMMIT() asm volatile("cp.async.commit_group;" ::: "memory")
#define CP_WAIT1()  asm volatile("cp.async.wait_group 1;" ::: "memory")
#define CP_WAIT0()  asm volatile("cp.async.wait_group 0;" ::: "memory")

__device__ __forceinline__ void stage_tile(uint32_t dstBase, const __half* src,
                                           int K, int k0, int tid) {
    int row = tid >> 2, c = tid & 3;
    #pragma unroll
    for (int i = 0; i < 2; i++) {
        int r = row + 64 * i;
        uint32_t doff = (uint32_t)(r * 64 + ((c ^ ((r >> 1) & 3)) << 4));
        CP_ASYNC16(dstBase + doff, src + (size_t)r * K + k0 + c * 8);
    }
}

// ================= 3-stage pipelined single-pass fp16 tensor GEMM =================
template<int RELU, int RES, int OUT, int SEGB>
__global__ __launch_bounds__(256, 2)
void tgemm_kernel(const __half* __restrict__ aH, const __half* __restrict__ bH,
                  const float* __restrict__ b0, const float* __restrict__ b1,
                  const float* __restrict__ b2,
                  const float* __restrict__ res, float* __restrict__ C,
                  __half* __restrict__ outH,
                  int M, int N, int K) {
    extern __shared__ char smem[];
    uint32_t sb = (uint32_t)__cvta_generic_to_shared(smem);

    int tid = threadIdx.x;
    int wid = tid >> 5, lane = tid & 31;
    int warpM = wid >> 2, warpN = wid & 3;
    int bn = blockIdx.x, bm = blockIdx.y;

    const __half* Ah = aH + (size_t)(bm * 128) * K;
    const __half* Bh = bH + (size_t)(bn * 128) * K;

    float acc[4][4][4];
    #pragma unroll
    for (int mt = 0; mt < 4; mt++)
        #pragma unroll
        for (int nt = 0; nt < 4; nt++)
            #pragma unroll
            for (int e = 0; e < 4; e++) acc[mt][nt][e] = 0.f;

    int nchunks = K >> 5;
    #pragma unroll
    for (int s = 0; s < 2; s++) {
        uint32_t sd = sb + s * 16384;
        stage_tile(sd,        Ah, K, s * 32, tid);
        stage_tile(sd + 8192, Bh, K, s * 32, tid);
        CP_COMMIT();
    }

    int slot = 0, nslot = 2;
    for (int c = 0; c < nchunks; c++) {
        if (c + 1 < nchunks) CP_WAIT1(); else CP_WAIT0();
        __syncthreads();
        if (c + 2 < nchunks) {
            uint32_t sd = sb + nslot * 16384;
            int k0 = (c + 2) * 32;
            stage_tile(sd,        Ah, K, k0, tid);
            stage_tile(sd + 8192, Bh, K, k0, tid);
            CP_COMMIT();
        }

        uint32_t st = sb + slot * 16384;
        #pragma unroll
        for (int ks = 0; ks < 2; ks++) {
            int cidx = ks * 2 + (lane >> 4);
            int arow = warpM * 64 + (lane & 15);
            int brow = warpN * 32 + (lane & 15);
            uint32_t a4[4][4];
            uint32_t b4[4][2];
            #pragma unroll
            for (int mt = 0; mt < 4; mt++) {
                int row = arow + mt * 16;
                ldsm4(a4[mt][0], a4[mt][1], a4[mt][2], a4[mt][3],
                      st + row * 64 + ((cidx ^ ((row >> 1) & 3)) << 4));
            }
            #pragma unroll
            for (int p = 0; p < 2; p++) {
                int row = brow + p * 16;
                uint32_t off = (uint32_t)(row * 64 + ((cidx ^ ((row >> 1) & 3)) << 4));
                uint32_t r0, r1, r2, r3;
                ldsm4(r0, r1, r2, r3, st + 8192 + off);
                b4[p*2][0] = r0; b4[p*2+1][0] = r1;
                b4[p*2][1] = r2; b4[p*2+1][1] = r3;
            }
            #pragma unroll
            for (int mt = 0; mt < 4; mt++)
                #pragma unroll
                for (int nt = 0; nt < 4; nt++)
                    mma16816(acc[mt][nt], a4[mt], b4[nt]);
        }
        slot = (slot == 2) ? 0 : slot + 1;
        nslot = (nslot == 2) ? 0 : nslot + 1;
    }

    #pragma unroll
    for (int mt = 0; mt < 4; mt++) {
        int r0 = bm * 128 + warpM * 64 + mt * 16 + (lane >> 2);
        #pragma unroll
        for (int nt = 0; nt < 4; nt++) {
            int cc = bn * 128 + warpN * 32 + nt * 8 + (lane & 3) * 2;
            const float* bp;
            int cb;
            if (SEGB) {
                int seg = cc >> 9;
                bp = (seg == 0) ? b0 : ((seg == 1) ? b1 : b2);
                cb = cc & 511;
            } else { bp = b0; cb = cc; }
            float2 bi = *(const float2*)(bp + cb);
            float2 o0 = make_float2(acc[mt][nt][0] + bi.x, acc[mt][nt][1] + bi.y);
            float2 o1 = make_float2(acc[mt][nt][2] + bi.x, acc[mt][nt][3] + bi.y);
            size_t g0 = (size_t)r0 * N + cc;
            size_t g1 = (size_t)(r0 + 8) * N + cc;
            if (RES) {
                float2 q0 = *(const float2*)(res + g0);
                float2 q1 = *(const float2*)(res + g1);
                o0.x += q0.x; o0.y += q0.y; o1.x += q1.x; o1.y += q1.y;
            }
            if (RELU) {
                o0.x = fmaxf(o0.x, 0.f); o0.y = fmaxf(o0.y, 0.f);
                o1.x = fmaxf(o1.x, 0.f); o1.y = fmaxf(o1.y, 0.f);
            }
            if (OUT == 0) {
                *(float2*)(C + g0) = o0;
                *(float2*)(C + g1) = o1;
            } else {
                *(uint32_t*)(outH + g0) = packhf(__float2half_rn(o0.x), __float2half_rn(o0.y));
                *(uint32_t*)(outH + g1) = packhf(__float2half_rn(o1.x), __float2half_rn(o1.y));
            }
        }
    }
}

// ---------------- all-weight fp16 conversion (once; QKV|WO|W1|W2) ----------------
__global__ void wconv_kernel(const float4* __restrict__ Wq, const float4* __restrict__ Wk,
                             const float4* __restrict__ Wv, const float4* __restrict__ Wo,
                             const float4* __restrict__ W1, const float4* __restrict__ W2) {
    int j = blockIdx.x * 256 + threadIdx.x;
    if (j >= WTOT_F4) return;
    const float4* src;
    if (j < 393216) {
        int layer = j / 196608;
        int r = j - layer * 196608;
        int seg = r >> 16, off = r & 65535;
        const float4* base = (seg == 0) ? Wq : ((seg == 1) ? Wk : Wv);
        src = base + layer * 65536 + off;
    } else if (j < 524288) {
        src = Wo + (j - 393216);
    } else if (j < 1048576) {
        src = W1 + (j - 524288);
    } else {
        src = W2 + (j - 1048576);
    }
    float4 f = *src;
    ((uint2*)g_wbH)[j] = make_uint2(
        packhf(__float2half_rn(f.x), __float2half_rn(f.y)),
        packhf(__float2half_rn(f.z), __float2half_rn(f.w)));
}

// ---------------- positional-embedding table (once) ----------------
__global__ void pe_kernel() {
    int i2 = blockIdx.x;
    double dv = exp(-(double)(2 * i2) * (9.210340371976184 / 512.0));
    const double TWO_PI = 6.283185307179586;
    const double INV2PI = 0.15915494309189535;
    for (int l = threadIdx.x; l < LL; l += 256) {
        double arg = (double)l * dv;
        double qd = rint(arg * INV2PI);
        double r = fma(-qd, TWO_PI, arg);
        float rf = (float)r;
        g_pe[l * DMODEL + 2 * i2]     = sinf(rf);
        g_pe[l * DMODEL + 2 * i2 + 1] = cosf(rf);
    }
}

// ---------------- threefry2x32 (JAX partitionable) ----------------
__device__ __forceinline__ void tf2x32(uint32_t k0, uint32_t k1,
                                       uint32_t x0, uint32_t x1,
                                       uint32_t& o0, uint32_t& o1) {
    uint32_t ks2 = k0 ^ k1 ^ 0x1BD11BDAu;
    uint32_t v0 = x0 + k0, v1 = x1 + k1;
#define TF_RND(r) { v0 += v1; v1 = (v1 << (r)) | (v1 >> (32 - (r))); v1 ^= v0; }
    TF_RND(13) TF_RND(15) TF_RND(26) TF_RND(6)   v0 += k1;  v1 += ks2 + 1u;
    TF_RND(17) TF_RND(29) TF_RND(16) TF_RND(24)  v0 += ks2; v1 += k0 + 2u;
    TF_RND(13) TF_RND(15) TF_RND(26) TF_RND(6)   v0 += k0;  v1 += k1 + 3u;
    TF_RND(17) TF_RND(29) TF_RND(16) TF_RND(24)  v0 += k1;  v1 += ks2 + 4u;
    TF_RND(13) TF_RND(15) TF_RND(26) TF_RND(6)   v0 += ks2; v1 += k0 + 5u;
#undef TF_RND
    o0 = v0; o1 = v1;
}

__global__ void sample_kernel(int layer) {
    int j = blockIdx.x * blockDim.x + threadIdx.x;
    if (j >= LL * UU) return;
    uint32_t a0, a1;
    tf2x32(0u, 42u, 0u, (uint32_t)layer, a0, a1);
    uint32_t k2a, k2b;
    tf2x32(a0, a1, 0u, 1u, k2a, k2b);
    uint32_t o0, o1;
    tf2x32(k2a, k2b, 0u, (uint32_t)j, o0, o1);
    g_samp[j] = (int)((o0 ^ o1) & 2047u);
}

// ---------------- input layernorm over C_IN=32 ----------------
__global__ void ln32_kernel(const float* __restrict__ x,
                            const float* __restrict__ g, const float* __restrict__ b) {
    int row  = blockIdx.x * 8 + (threadIdx.x >> 5);
    int lane = threadIdx.x & 31;
    float v = x[(size_t)row * CIN + lane];
    float s = v;
    #pragma unroll
    for (int o = 16; o; o >>= 1) s += __shfl_xor_sync(~0u, s, o);
    float m = s * (1.f / 32.f);
    float d = v - m;
    float ss = d * d;
    #pragma unroll
    for (int o = 16; o; o >>= 1) ss += __shfl_xor_sync(~0u, ss, o);
    float r = rsqrtf(ss * (1.f / 32.f) + 1e-5f);
    g_xln[(size_t)row * CIN + lane] = d * r * g[lane] + b[lane];
}

// ---------------- token conv + pe table + time proj ----------------
__global__ void embed_kernel(const float* __restrict__ tfeat,
                             const float* __restrict__ Wtok,
                             const float* __restrict__ Wtime,
                             const float* __restrict__ btime) {
    int bl = blockIdx.x;
    int l = bl & (LL - 1);
    int b = bl >> 11;
    __shared__ float xs[96];
    __shared__ float tf[4];
    int tid = threadIdx.x; // 128
    if (tid < 96) {
        int w = tid / 32, c = tid % 32;
        int lsrc = (l - 1 + w + LL) & (LL - 1);
        xs[tid] = g_xln[((size_t)b * LL + lsrc) * CIN + c];
    }
    if (tid < 4) tf[tid] = tfeat[((size_t)b * LL + l) * 4 + tid];
    __syncthreads();
    for (int m = tid; m < DMODEL; m += 128) {
        float acc = btime[m];
        #pragma unroll 8
        for (int wc = 0; wc < 96; wc++) acc += xs[wc] * Wtok[wc * DMODEL + m];
        #pragma unroll
        for (int t = 0; t < 4; t++) acc += tf[t] * Wtime[m * 4 + t];
        float v = acc + g_pe[l * DMODEL + m];
        size_t idx = ((size_t)b * LL + l) * DMODEL + m;
        g_h[idx] = v;
        g_aH[idx] = __float2half_rn(v);
    }
}

// ---------------- M scores (MLP=24 front-batched gathers) ----------------
__global__ void mscore_kernel() {
    int wid  = (blockIdx.x * blockDim.x + threadIdx.x) >> 5;
    int lane = threadIdx.x & 31;
    if (wid >= BB * NH * LL) return;
    int l = wid & (LL - 1);
    int h = (wid >> 11) & (NH - 1);
    int b = wid >> 14;
    const float* qr = g_qkv + ((size_t)b * LL + l) * 1536 + h * 64;
    float q0 = qr[lane * 2], q1 = qr[lane * 2 + 1];
    int idxs[UU];
    #pragma unroll
    for (int s = 0; s < UU; s++) idxs[s] = g_samp[l * UU + s];
    float vv[UU];
    #pragma unroll
    for (int s = 0; s < UU; s++) {
        const float* kr = g_qkv + ((size_t)b * LL + idxs[s]) * 1536 + 512 + h * 64;
        float2 kf = *(const float2*)(kr + lane * 2);
        vv[s] = q0 * kf.x + q1 * kf.y;
    }
    float mx = -INFINITY, sm = 0.f;
    #pragma unroll
    for (int s = 0; s < UU; s++) {
        float v = vv[s];
        #pragma unroll
        for (int o = 16; o; o >>= 1) v += __shfl_xor_sync(~0u, v, o);
        mx = fmaxf(mx, v);
        sm += v;
    }
    if (lane == 0)
        g_M[((size_t)(b * NH + h)) * LL + l] = mx - sm * (1.0f / (float)LL);
}

// ---------------- top-24 per (b,h), JAX tie semantics ----------------
__global__ void topk_kernel() {
    int bh = blockIdx.x;
    int tid = threadIdx.x;   // 256
    __shared__ float sv[LL];
    __shared__ float rv[256];
    __shared__ int   ri[256];
    for (int i = tid; i < LL; i += 256) sv[i] = g_M[(size_t)bh * LL + i];
    __syncthreads();
    for (int t = 0; t < UU; t++) {
        float bvv = -INFINITY; int bi = LL;
        for (int i = tid; i < LL; i += 256) {
            float v = sv[i];
            if (v > bvv || (v == bvv && i < bi)) { bvv = v; bi = i; }
        }
        rv[tid] = bvv; ri[tid] = bi;
        __syncthreads();
        for (int s = 128; s > 0; s >>= 1) {
            if (tid < s) {
                float v2 = rv[tid + s]; int i2 = ri[tid + s];
                if (v2 > rv[tid] || (v2 == rv[tid] && i2 < ri[tid])) { rv[tid] = v2; ri[tid] = i2; }
            }
            __syncthreads();
        }
        if (tid == 0) { g_idxtop[bh * UU + t] = ri[0]; sv[ri[0]] = -INFINITY; }
        __syncthreads();
    }
}

// ---------------- split-K attention phase 1: per-(bh, key-tile) partials ----------
__global__ __launch_bounds__(256)
void attnpart_kernel() {    // grid (64, 8), 256 threads
    int bh = blockIdx.x, kt = blockIdx.y;
    int h = bh & 7, b = bh >> 3;
    int tid = threadIdx.x;
    int wid = tid >> 5, lane = tid & 31;
    int d = tid & 63, part = tid >> 6;
    size_t bL = (size_t)b * LL;

    __shared__ float qs[UU * 64];
    __shared__ float sc[UU][257];
    __shared__ float mt_[UU], lt_[UU];
    __shared__ float svs[4][64];

    for (int i = tid; i < UU * 64; i += 256) {
        int u = i >> 6, dd = i & 63;
        qs[i] = g_qkv[(bL + g_idxtop[bh * UU + u]) * 1536 + h * 64 + dd];
    }
    __syncthreads();

    int k = kt * 256 + tid;
    float4 kr[16];
    const float4* kp = (const float4*)(g_qkv + (bL + k) * 1536 + 512 + h * 64);
    #pragma unroll
    for (int i = 0; i < 16; i++) kr[i] = kp[i];
    #pragma unroll 4
    for (int u = 0; u < UU; u++) {
        const float4* qp = (const float4*)(qs + u * 64);
        float s = 0.f;
        #pragma unroll
        for (int i = 0; i < 16; i++) {
            float4 q4 = qp[i];
            s += q4.x * kr[i].x + q4.y * kr[i].y + q4.z * kr[i].z + q4.w * kr[i].w;
        }
        sc[u][tid] = s * 0.125f;
    }
    __syncthreads();

    #pragma unroll
    for (int j = 0; j < 3; j++) {
        int u = wid * 3 + j;
        float tm = -INFINITY;
        #pragma unroll
        for (int i = 0; i < 8; i++) tm = fmaxf(tm, sc[u][lane + 32 * i]);
        #pragma unroll
        for (int o = 16; o; o >>= 1) tm = fmaxf(tm, __shfl_xor_sync(~0u, tm, o));
        if (lane == 0) mt_[u] = tm;
    }
    __syncthreads();

    #pragma unroll 4
    for (int u = 0; u < UU; u++)
        sc[u][tid] = expf(sc[u][tid] - mt_[u]);
    __syncthreads();

    #pragma unroll
    for (int j = 0; j < 3; j++) {
        int u = wid * 3 + j;
        float ts = 0.f;
        #pragma unroll
        for (int i = 0; i < 8; i++) ts += sc[u][lane + 32 * i];
        #pragma unroll
        for (int o = 16; o; o >>= 1) ts += __shfl_xor_sync(~0u, ts, o);
        if (lane == 0) lt_[u] = ts;
    }

    float acc[UU];
    #pragma unroll
    for (int u = 0; u < UU; u++) acc[u] = 0.f;
    float vsum = 0.f;
    for (int kk = part; kk < 256; kk += 4) {
        float v = g_qkv[(bL + kt * 256 + kk) * 1536 + 1024 + h * 64 + d];
        vsum += v;
        #pragma unroll
        for (int u = 0; u < UU; u++) acc[u] += sc[u][kk] * v;
    }
    __syncthreads();

    #pragma unroll 4
    for (int u = 0; u < UU; u++) sc[u][part * 64 + d] = acc[u];
    svs[part][d] = vsum;
    __syncthreads();

    #pragma unroll
    for (int uu = 0; uu < 6; uu++) {
        int u = uu * 4 + part;
        float tot = sc[u][d] + sc[u][64 + d] + sc[u][128 + d] + sc[u][192 + d];
        g_pacc[(((size_t)bh * 8 + kt) * UU + u) * HD + d] = tot;
    }
    if (tid < UU) {
        g_pm[(bh * 8 + kt) * UU + tid] = mt_[tid];
        g_pl[(bh * 8 + kt) * UU + tid] = lt_[tid];
    }
    if (tid < 64)
        g_pvs[(bh * 8 + kt) * HD + tid] =
            svs[0][tid] + svs[1][tid] + svs[2][tid] + svs[3][tid];
}

// ---------------- split-K attention phase 2: deterministic combine ----------------
__global__ void attncomb_kernel() {   // grid 64, 256 threads
    int bh = blockIdx.x;
    int tid = threadIdx.x;
    int d = tid & 63, ug = tid >> 6;
    #pragma unroll
    for (int uu = 0; uu < 6; uu++) {
        int u = uu * 4 + ug;
        float m = -INFINITY;
        #pragma unroll
        for (int kt = 0; kt < 8; kt++)
            m = fmaxf(m, g_pm[(bh * 8 + kt) * UU + u]);
        float denom = 0.f, numer = 0.f;
        #pragma unroll
        for (int kt = 0; kt < 8; kt++) {
            float e = expf(g_pm[(bh * 8 + kt) * UU + u] - m);
            denom += g_pl[(bh * 8 + kt) * UU + u] * e;
            numer += g_pacc[(((size_t)bh * 8 + kt) * UU + u) * HD + d] * e;
        }
        g_upd[((size_t)bh * UU + u) * HD + d] = numer / denom;
    }
    if (tid < 64) {
        float s = 0.f;
        #pragma unroll
        for (int kt = 0; kt < 8; kt++) s += g_pvs[(bh * 8 + kt) * HD + tid];
        g_vmean[bh * HD + tid] = s * (1.0f / (float)LL);
    }
}

// ---------------- broadcast vmean into fp16 attn buffer ----------------
__global__ void fill_kernel() {
    size_t i = (size_t)blockIdx.x * 256 + threadIdx.x;
    size_t e = i * 2;
    int d = (int)(e & 63);
    int h = (int)((e >> 6) & 7);
    int b = (int)(e >> 20);
    float v0 = g_vmean[(b * NH + h) * HD + d];
    float v1 = g_vmean[(b * NH + h) * HD + d + 1];
    *(uint32_t*)(g_aH + e) = packhf(__float2half_rn(v0), __float2half_rn(v1));
}

// ---------------- scatter updated rows (fp16) ----------------
__global__ void scatter_kernel() {
    int bid = blockIdx.x;
    int u = bid % UU;
    int bh = bid / UU;
    int h = bh & (NH - 1), b = bh >> 3;
    int qi = g_idxtop[bh * UU + u];
    float v = g_upd[(size_t)bid * HD + threadIdx.x];
    size_t idx = (((size_t)b * LL + qi) * NH + h) * HD + threadIdx.x;
    g_aH[idx] = __float2half_rn(v);
}

// ---------------- layernorm over 512 (optionally emits fp16) ----------------
__global__ void ln512_kernel(const float* __restrict__ in, float* __restrict__ out,
                             const float* __restrict__ g, const float* __restrict__ b,
                             size_t strideIn, size_t strideOut,
                             __half* __restrict__ hOut) {
    int row = blockIdx.x;
    int tid = threadIdx.x;  // 128
    const float* x = in + (size_t)row * strideIn;
    float4 v = *(const float4*)(x + tid * 4);
    float s  = v.x + v.y + v.z + v.w;
    float ss = v.x*v.x + v.y*v.y + v.z*v.z + v.w*v.w;
    __shared__ float rs[4], rss[4];
    #pragma unroll
    for (int o = 16; o; o >>= 1) {
        s  += __shfl_xor_sync(~0u, s, o);
        ss += __shfl_xor_sync(~0u, ss, o);
    }
    int w = tid >> 5, lane = tid & 31;
    if (lane == 0) { rs[w] = s; rss[w] = ss; }
    __syncthreads();
    s  = rs[0] + rs[1] + rs[2] + rs[3];
    ss = rss[0] + rss[1] + rss[2] + rss[3];
    float m = s * (1.f / 512.f);
    float var = ss * (1.f / 512.f) - m * m;
    float r = rsqrtf(var + 1e-5f);
    float4 gg = *(const float4*)(g + tid * 4);
    float4 bb = *(const float4*)(b + tid * 4);
    float4 o4;
    o4.x = (v.x - m) * r * gg.x + bb.x;
    o4.y = (v.y - m) * r * gg.y + bb.y;
    o4.z = (v.z - m) * r * gg.z + bb.z;
    o4.w = (v.w - m) * r * gg.w + bb.w;
    *(float4*)(out + (size_t)row * strideOut + tid * 4) = o4;
    if (hOut) {
        size_t e = (size_t)row * DMODEL + tid * 4;
        *(uint2*)(hOut + e) = make_uint2(
            packhf(__float2half_rn(o4.x), __float2half_rn(o4.y)),
            packhf(__float2half_rn(o4.z), __float2half_rn(o4.w)));
    }
}

// ---------------- tail: layer-2 post-attention for the LAST row of each batch -----
__global__ __launch_bounds__(512)
void tail_kernel(const float* __restrict__ Wo, const float* __restrict__ bo,
                 const float* __restrict__ W1, const float* __restrict__ b1,
                 const float* __restrict__ W2, const float* __restrict__ b2,
                 const float* __restrict__ g1v, const float* __restrict__ be1v,
                 const float* __restrict__ g2v, const float* __restrict__ be2v,
                 const float* __restrict__ genc, const float* __restrict__ benc,
                 const float* __restrict__ Wpre, const float* __restrict__ bpre,
                 const float* __restrict__ Wfc,  const float* __restrict__ bfc,
                 float* __restrict__ out) {
    int b = blockIdx.x;           // 8
    int tid = threadIdx.x;        // 512
    int wid = tid >> 5, lane = tid & 31;
    __shared__ float av[512];
    __shared__ float hA[512];
    __shared__ float hid[2048];
    __shared__ float rs[16], rss[16];

    {
        int h = tid >> 6, d = tid & 63;
        float v = g_vmean[(b * NH + h) * HD + d];
        #pragma unroll 4
        for (int u = 0; u < UU; u++)
            if (g_idxtop[(b * NH + h) * UU + u] == LL - 1)
                v = g_upd[((size_t)(b * NH + h) * UU + u) * HD + d];
        av[tid] = v;
    }
    __syncthreads();

    float t = bo[tid];
    {
        const float4* wr = (const float4*)(Wo + (size_t)tid * 512);
        const float4* ar = (const float4*)av;
        #pragma unroll 8
        for (int k = 0; k < 128; k++) {
            float4 w4 = wr[k], a4 = ar[k];
            t += a4.x * w4.x + a4.y * w4.y + a4.z * w4.z + a4.w * w4.w;
        }
        t += g_h[((size_t)b * LL + (LL - 1)) * DMODEL + tid];
    }

    {
        float s = t, ss = t * t;
        #pragma unroll
        for (int o = 16; o; o >>= 1) {
            s  += __shfl_xor_sync(~0u, s, o);
            ss += __shfl_xor_sync(~0u, ss, o);
        }
        if (lane == 0) { rs[wid] = s; rss[wid] = ss; }
        __syncthreads();
        float S = 0.f, SS = 0.f;
        #pragma unroll
        for (int w = 0; w < 16; w++) { S += rs[w]; SS += rss[w]; }
        float m = S * (1.f / 512.f);
        float r = rsqrtf(SS * (1.f / 512.f) - m * m + 1e-5f);
        hA[tid] = (t - m) * r * g1v[tid] + be1v[tid];
        __syncthreads();
    }

    #pragma unroll
    for (int jj = 0; jj < 4; jj++) {
        int j = tid + jj * 512;
        float acc = b1[j];
        const float4* wr = (const float4*)(W1 + (size_t)j * 512);
        const float4* ar = (const float4*)hA;
        #pragma unroll 8
        for (int k = 0; k < 128; k++) {
            float4 w4 = wr[k], a4 = ar[k];
            acc += a4.x * w4.x + a4.y * w4.y + a4.z * w4.z + a4.w * w4.w;
        }
        hid[j] = fmaxf(acc, 0.f);
    }
    __syncthreads();

    float t2;
    {
        float acc = b2[tid];
        const float4* wr = (const float4*)(W2 + (size_t)tid * 2048);
        const float4* ar = (const float4*)hid;
        #pragma unroll 8
        for (int k = 0; k < 512; k++) {
            float4 w4 = wr[k], a4 = ar[k];
            acc += a4.x * w4.x + a4.y * w4.y + a4.z * w4.z + a4.w * w4.w;
        }
        t2 = hA[tid] + acc;
    }
    __syncthreads();

    {
        float s = t2, ss = t2 * t2;
        #pragma unroll
        for (int o = 16; o; o >>= 1) {
            s  += __shfl_xor_sync(~0u, s, o);
            ss += __shfl_xor_sync(~0u, ss, o);
        }
        if (lane == 0) { rs[wid] = s; rss[wid] = ss; }
        __syncthreads();
        float S = 0.f, SS = 0.f;
        #pragma unroll
        for (int w = 0; w < 16; w++) { S += rs[w]; SS += rss[w]; }
        float m = S * (1.f / 512.f);
        float r = rsqrtf(SS * (1.f / 512.f) - m * m + 1e-5f);
        float hB = (t2 - m) * r * g2v[tid] + be2v[tid];
        __syncthreads();

        s = hB; ss = hB * hB;
        #pragma unroll
        for (int o = 16; o; o >>= 1) {
            s  += __shfl_xor_sync(~0u, s, o);
            ss += __shfl_xor_sync(~0u, ss, o);
        }
        if (lane == 0) { rs[wid] = s; rss[wid] = ss; }
        __syncthreads();
        S = 0.f; SS = 0.f;
        #pragma unroll
        for (int w = 0; w < 16; w++) { S += rs[w]; SS += rss[w]; }
        m = S * (1.f / 512.f);
        r = rsqrtf(SS * (1.f / 512.f) - m * m + 1e-5f);
        av[tid] = (hB - m) * r * genc[tid] + benc[tid];
        __syncthreads();
    }

    float contrib = 0.f;
    if (tid < 256) {
        float acc = bpre[tid];
        const float4* wr = (const float4*)(Wpre + (size_t)tid * 512);
        const float4* ar = (const float4*)av;
        #pragma unroll 8
        for (int k = 0; k < 128; k++) {
            float4 w4 = wr[k], a4 = ar[k];
            acc += a4.x * w4.x + a4.y * w4.y + a4.z * w4.z + a4.w * w4.w;
        }
        contrib = fmaxf(acc, 0.f) * Wfc[tid];
    }
    {
        float s = contrib;
        #pragma unroll
        for (int o = 16; o; o >>= 1) s += __shfl_xor_sync(~0u, s, o);
        if (lane == 0) rs[wid] = s;
        __syncthreads();
        if (tid == 0) {
            float S = 0.f;
            #pragma unroll
            for (int w = 0; w < 16; w++) S += rs[w];
            out[b] = S + bfc[0];
        }
    }
}

// ---------------- host orchestration ----------------
#define SMEM_GEMM 49152

extern "C" void kernel_launch(void* const* d_in, const int* in_sizes, int n_in,
                              void* d_out, int out_size) {
    const float* x      = (const float*)d_in[0];
    const float* tfeat  = (const float*)d_in[1];
    const float* g_in   = (const float*)d_in[2];
    const float* b_in   = (const float*)d_in[3];
    const float* W_tok  = (const float*)d_in[4];
    const float* W_time = (const float*)d_in[5];
    const float* b_time = (const float*)d_in[6];
    const float* Wq     = (const float*)d_in[7];
    const float* bq     = (const float*)d_in[8];
    const float* Wk     = (const float*)d_in[9];
    const float* bk     = (const float*)d_in[10];
    const float* Wv     = (const float*)d_in[11];
    const float* bv     = (const float*)d_in[12];
    const float* Wo     = (const float*)d_in[13];
    const float* bo     = (const float*)d_in[14];
    const float* W1     = (const float*)d_in[15];
    const float* b1     = (const float*)d_in[16];
    const float* W2     = (const float*)d_in[17];
    const float* b2     = (const float*)d_in[18];
    const float* g1     = (const float*)d_in[19];
    const float* be1    = (const float*)d_in[20];
    const float* g2     = (const float*)d_in[21];
    const float* be2    = (const float*)d_in[22];
    const float* g_enc  = (const float*)d_in[23];
    const float* b_enc  = (const float*)d_in[24];
    const float* W_pre  = (const float*)d_in[25];
    const float* b_pre  = (const float*)d_in[26];
    const float* W_fc   = (const float*)d_in[27];
    const float* b_fc   = (const float*)d_in[28];

    float *h, *qkv;
    __half *aH, *fH, *wbH;
    cudaGetSymbolAddress((void**)&h,   g_h);
    cudaGetSymbolAddress((void**)&qkv, g_qkv);
    cudaGetSymbolAddress((void**)&aH,  g_aH);
    cudaGetSymbolAddress((void**)&fH,  g_fH);
    cudaGetSymbolAddress((void**)&wbH, g_wbH);

    cudaFuncSetAttribute(tgemm_kernel<0,0,0,1>, cudaFuncAttributeMaxDynamicSharedMemorySize, SMEM_GEMM);
    cudaFuncSetAttribute(tgemm_kernel<1,0,1,0>, cudaFuncAttributeMaxDynamicSharedMemorySize, SMEM_GEMM);
    cudaFuncSetAttribute(tgemm_kernel<0,1,0,0>, cudaFuncAttributeMaxDynamicSharedMemorySize, SMEM_GEMM);

    pe_kernel<<<256, 256>>>();
    ln32_kernel<<<MROWS / 8, 256>>>(x, g_in, b_in);
    embed_kernel<<<MROWS, 128>>>(tfeat, W_tok, W_time, b_time);
    wconv_kernel<<<WTOT_F4 / 256, 256>>>((const float4*)Wq, (const float4*)Wk,
                                         (const float4*)Wv, (const float4*)Wo,
                                         (const float4*)W1, (const float4*)W2);

    dim3 gQKV(1536 / 128, MROWS / 128);
    dim3 gO(DMODEL / 128, MROWS / 128);
    dim3 gF1(DFF / 128,  MROWS / 128);
    dim3 gF2(DMODEL / 128, MROWS / 128);

    for (int i = 0; i < NE; i++) {
        size_t bOff  = (size_t)i * DMODEL;
        size_t b1Off = (size_t)i * DFF;
        size_t qkvW  = (size_t)i * QKV_PER_LAYER;
        size_t woW   = WO_OFF + (size_t)i * DMODEL * DMODEL;
        size_t w1W   = W1_OFF + (size_t)i * DFF * DMODEL;
        size_t w2W   = W2_OFF + (size_t)i * DFF * DMODEL;

        sample_kernel<<<(LL * UU + 255) / 256, 256>>>(i);

        tgemm_kernel<0,0,0,1><<<gQKV, 256, SMEM_GEMM>>>(
            aH, wbH + qkvW,
            bq + bOff, bk + bOff, bv + bOff, nullptr, qkv, nullptr,
            MROWS, 1536, DMODEL);

        mscore_kernel<<<(BB * NH * LL * 32) / 256, 256>>>();
        topk_kernel<<<BB * NH, 256>>>();
        attnpart_kernel<<<dim3(BB * NH, 8), 256>>>();
        attncomb_kernel<<<BB * NH, 256>>>();

        if (i == 0) {
            fill_kernel<<<(MROWS * DMODEL / 2) / 256, 256>>>();
            scatter_kernel<<<BB * NH * UU, HD>>>();

            tgemm_kernel<0,1,0,0><<<gO, 256, SMEM_GEMM>>>(
                aH, wbH + woW,
                bo + bOff, nullptr, nullptr, h, h, nullptr,
                MROWS, DMODEL, DMODEL);
            ln512_kernel<<<MROWS, 128>>>(h, h, g1 + bOff, be1 + bOff, DMODEL, DMODEL, aH);

            tgemm_kernel<1,0,1,0><<<gF1, 256, SMEM_GEMM>>>(
                aH, wbH + w1W,
                b1 + b1Off, nullptr, nullptr, nullptr, nullptr, fH,
                MROWS, DFF, DMODEL);
            tgemm_kernel<0,1,0,0><<<gF2, 256, SMEM_GEMM>>>(
                fH, wbH + w2W,
                b2 + bOff, nullptr, nullptr, h, h, nullptr,
                MROWS, DMODEL, DFF);
            ln512_kernel<<<MROWS, 128>>>(h, h, g2 + bOff, be2 + bOff, DMODEL, DMODEL, aH);
        } else {
            // layer 2: only row L-1 per batch reaches the output -> fp32 tail
            tail_kernel<<<BB, 512>>>(
                Wo + (size_t)i * DMODEL * DMODEL, bo + bOff,
                W1 + (size_t)i * DFF * DMODEL, b1 + b1Off,
                W2 + (size_t)i * DMODEL * DFF, b2 + bOff,
                g1 + bOff, be1 + bOff, g2 + bOff, be2 + bOff,
                g_enc, b_enc, W_pre, b_pre, W_fc, b_fc, (float*)d_out);
        }
    }
}

// round 17
// speedup vs baseline: 1.6294x; 1.0681x over previous
#include <cuda_runtime.h>
#include <cuda_fp16.h>
#include <math.h>
#include <stdint.h>
#include <stddef.h>

// ---------------- problem dims (fixed) ----------------
#define BB   8
#define LL   2048
#define CIN  32
#define DMODEL 512
#define DFF  2048
#define NH   8
#define HD   64
#define NE   2
#define UU   24
#define MROWS (BB*LL)      // 16384

// converted-weight layout (fp16 element offsets)
#define QKV_PER_LAYER (1536*512)
#define WO_OFF   1572864
#define W1_OFF   2097152
#define W2_OFF   4194304
#define WTOT     6291456
#define WTOT_F4  1572864

// ---------------- scratch ----------------
__device__ float g_xln [MROWS*CIN];
__device__ float g_h   [(size_t)MROWS*DMODEL];
__device__ float g_qkv [(size_t)MROWS*1536];
__device__ float g_M   [BB*NH*LL];
__device__ int   g_samp[LL*UU];
__device__ int   g_idxtop[BB*NH*UU];
__device__ float g_vmean[BB*NH*HD];
__device__ float g_upd [BB*NH*UU*HD];
__device__ float g_pe  [LL*DMODEL];
// split-K attention partials
__device__ float g_pacc[(size_t)BB*NH*8*UU*HD];
__device__ float g_pm  [BB*NH*8*UU];
__device__ float g_pl  [BB*NH*8*UU];
__device__ float g_pvs [BB*NH*8*HD];
__device__ __half g_aH[(size_t)MROWS*DMODEL];
__device__ __half g_fH[(size_t)MROWS*DFF];
__device__ __half g_wbH[WTOT];

// ================= helpers =================
__device__ __forceinline__ uint32_t packhf(__half a, __half b) {
    __half2 t = __halves2half2(a, b);
    return *reinterpret_cast<uint32_t*>(&t);
}
__device__ __forceinline__ void mma16816(float* c, const uint32_t* a, const uint32_t* b) {
    asm volatile(
        "mma.sync.aligned.m16n8k16.row.col.f32.f16.f16.f32 "
        "{%0,%1,%2,%3}, {%4,%5,%6,%7}, {%8,%9}, {%0,%1,%2,%3};"
        : "+f"(c[0]), "+f"(c[1]), "+f"(c[2]), "+f"(c[3])
        : "r"(a[0]), "r"(a[1]), "r"(a[2]), "r"(a[3]), "r"(b[0]), "r"(b[1]));
}
__device__ __forceinline__ void ldsm4(uint32_t& r0, uint32_t& r1, uint32_t& r2, uint32_t& r3,
                                      uint32_t addr) {
    asm volatile("ldmatrix.sync.aligned.m8n8.x4.shared.b16 {%0,%1,%2,%3}, [%4];"
                 : "=r"(r0), "=r"(r1), "=r"(r2), "=r"(r3) : "r"(addr));
}
#define CP_ASYNC16(dst, src) \
    asm volatile("cp.async.ca.shared.global [%0], [%1], 16;" :: "r"(dst), "l"(src))
#define CP_COMMIT() asm volatile("cp.async.commit_group;" ::: "memory")
#define CP_WAIT1()  asm volatile("cp.async.wait_group 1;" ::: "memory")
#define CP_WAIT0()  asm volatile("cp.async.wait_group 0;" ::: "memory")

// 128-row x 64-half (128B) tile, XOR swizzle over 8 16B chunks
__device__ __forceinline__ void stage_tile64(uint32_t dstBase, const __half* src,
                                             int K, int k0, int tid) {
    int row = tid >> 3, c = tid & 7;
    #pragma unroll
    for (int i = 0; i < 4; i++) {
        int r = row + 32 * i;
        uint32_t doff = (uint32_t)(r * 128 + ((c ^ (r & 7)) << 4));
        CP_ASYNC16(dstBase + doff, src + (size_t)r * K + k0 + c * 8);
    }
}

// ================= 3-stage pipelined single-pass fp16 tensor GEMM, BK=64 ==========
// Stage = 32KB (A|B of a BK=64 chunk). 3 stages/CTA, 2 CTAs/SM.
template<int RELU, int RES, int OUT, int SEGB>
__global__ __launch_bounds__(256, 2)
void tgemm_kernel(const __half* __restrict__ aH, const __half* __restrict__ bH,
                  const float* __restrict__ b0, const float* __restrict__ b1,
                  const float* __restrict__ b2,
                  const float* __restrict__ res, float* __restrict__ C,
                  __half* __restrict__ outH,
                  int M, int N, int K) {
    extern __shared__ char smem[];
    uint32_t sb = (uint32_t)__cvta_generic_to_shared(smem);

    int tid = threadIdx.x;
    int wid = tid >> 5, lane = tid & 31;
    int warpM = wid >> 2, warpN = wid & 3;
    int bn = blockIdx.x, bm = blockIdx.y;

    const __half* Ah = aH + (size_t)(bm * 128) * K;
    const __half* Bh = bH + (size_t)(bn * 128) * K;

    float acc[4][4][4];
    #pragma unroll
    for (int mt = 0; mt < 4; mt++)
        #pragma unroll
        for (int nt = 0; nt < 4; nt++)
            #pragma unroll
            for (int e = 0; e < 4; e++) acc[mt][nt][e] = 0.f;

    int nchunks = K >> 6;
    #pragma unroll
    for (int s = 0; s < 2; s++) {
        uint32_t sd = sb + s * 32768;
        stage_tile64(sd,         Ah, K, s * 64, tid);
        stage_tile64(sd + 16384, Bh, K, s * 64, tid);
        CP_COMMIT();
    }

    int slot = 0, nslot = 2;
    for (int c = 0; c < nchunks; c++) {
        if (c + 1 < nchunks) CP_WAIT1(); else CP_WAIT0();
        __syncthreads();
        if (c + 2 < nchunks) {
            uint32_t sd = sb + nslot * 32768;
            int k0 = (c + 2) * 64;
            stage_tile64(sd,         Ah, K, k0, tid);
            stage_tile64(sd + 16384, Bh, K, k0, tid);
            CP_COMMIT();
        }

        uint32_t st = sb + slot * 32768;
        #pragma unroll
        for (int ks = 0; ks < 4; ks++) {
            int cidx = ks * 2 + (lane >> 4);          // 0..7
            int arow = warpM * 64 + (lane & 15);
            int brow = warpN * 32 + (lane & 15);
            uint32_t a4[4][4];
            uint32_t b4[4][2];
            #pragma unroll
            for (int mt = 0; mt < 4; mt++) {
                int row = arow + mt * 16;
                ldsm4(a4[mt][0], a4[mt][1], a4[mt][2], a4[mt][3],
                      st + row * 128 + ((cidx ^ (row & 7)) << 4));
            }
            #pragma unroll
            for (int p = 0; p < 2; p++) {
                int row = brow + p * 16;
                uint32_t off = (uint32_t)(row * 128 + ((cidx ^ (row & 7)) << 4));
                uint32_t r0, r1, r2, r3;
                ldsm4(r0, r1, r2, r3, st + 16384 + off);
                b4[p*2][0] = r0; b4[p*2+1][0] = r1;
                b4[p*2][1] = r2; b4[p*2+1][1] = r3;
            }
            #pragma unroll
            for (int mt = 0; mt < 4; mt++)
                #pragma unroll
                for (int nt = 0; nt < 4; nt++)
                    mma16816(acc[mt][nt], a4[mt], b4[nt]);
        }
        slot = (slot == 2) ? 0 : slot + 1;
        nslot = (nslot == 2) ? 0 : nslot + 1;
    }

    #pragma unroll
    for (int mt = 0; mt < 4; mt++) {
        int r0 = bm * 128 + warpM * 64 + mt * 16 + (lane >> 2);
        #pragma unroll
        for (int nt = 0; nt < 4; nt++) {
            int cc = bn * 128 + warpN * 32 + nt * 8 + (lane & 3) * 2;
            const float* bp;
            int cb;
            if (SEGB) {
                int seg = cc >> 9;
                bp = (seg == 0) ? b0 : ((seg == 1) ? b1 : b2);
                cb = cc & 511;
            } else { bp = b0; cb = cc; }
            float2 bi = *(const float2*)(bp + cb);
            float2 o0 = make_float2(acc[mt][nt][0] + bi.x, acc[mt][nt][1] + bi.y);
            float2 o1 = make_float2(acc[mt][nt][2] + bi.x, acc[mt][nt][3] + bi.y);
            size_t g0 = (size_t)r0 * N + cc;
            size_t g1 = (size_t)(r0 + 8) * N + cc;
            if (RES) {
                float2 q0 = *(const float2*)(res + g0);
                float2 q1 = *(const float2*)(res + g1);
                o0.x += q0.x; o0.y += q0.y; o1.x += q1.x; o1.y += q1.y;
            }
            if (RELU) {
                o0.x = fmaxf(o0.x, 0.f); o0.y = fmaxf(o0.y, 0.f);
                o1.x = fmaxf(o1.x, 0.f); o1.y = fmaxf(o1.y, 0.f);
            }
            if (OUT == 0) {
                *(float2*)(C + g0) = o0;
                *(float2*)(C + g1) = o1;
            } else {
                *(uint32_t*)(outH + g0) = packhf(__float2half_rn(o0.x), __float2half_rn(o0.y));
                *(uint32_t*)(outH + g1) = packhf(__float2half_rn(o1.x), __float2half_rn(o1.y));
            }
        }
    }
}

// ---------------- all-weight fp16 conversion (once; QKV|WO|W1|W2) ----------------
__global__ void wconv_kernel(const float4* __restrict__ Wq, const float4* __restrict__ Wk,
                             const float4* __restrict__ Wv, const float4* __restrict__ Wo,
                             const float4* __restrict__ W1, const float4* __restrict__ W2) {
    int j = blockIdx.x * 256 + threadIdx.x;
    if (j >= WTOT_F4) return;
    const float4* src;
    if (j < 393216) {
        int layer = j / 196608;
        int r = j - layer * 196608;
        int seg = r >> 16, off = r & 65535;
        const float4* base = (seg == 0) ? Wq : ((seg == 1) ? Wk : Wv);
        src = base + layer * 65536 + off;
    } else if (j < 524288) {
        src = Wo + (j - 393216);
    } else if (j < 1048576) {
        src = W1 + (j - 524288);
    } else {
        src = W2 + (j - 1048576);
    }
    float4 f = *src;
    ((uint2*)g_wbH)[j] = make_uint2(
        packhf(__float2half_rn(f.x), __float2half_rn(f.y)),
        packhf(__float2half_rn(f.z), __float2half_rn(f.w)));
}

// ---------------- positional-embedding table (once) ----------------
__global__ void pe_kernel() {
    int i2 = blockIdx.x;
    double dv = exp(-(double)(2 * i2) * (9.210340371976184 / 512.0));
    const double TWO_PI = 6.283185307179586;
    const double INV2PI = 0.15915494309189535;
    for (int l = threadIdx.x; l < LL; l += 256) {
        double arg = (double)l * dv;
        double qd = rint(arg * INV2PI);
        double r = fma(-qd, TWO_PI, arg);
        float rf = (float)r;
        g_pe[l * DMODEL + 2 * i2]     = sinf(rf);
        g_pe[l * DMODEL + 2 * i2 + 1] = cosf(rf);
    }
}

// ---------------- threefry2x32 (JAX partitionable) ----------------
__device__ __forceinline__ void tf2x32(uint32_t k0, uint32_t k1,
                                       uint32_t x0, uint32_t x1,
                                       uint32_t& o0, uint32_t& o1) {
    uint32_t ks2 = k0 ^ k1 ^ 0x1BD11BDAu;
    uint32_t v0 = x0 + k0, v1 = x1 + k1;
#define TF_RND(r) { v0 += v1; v1 = (v1 << (r)) | (v1 >> (32 - (r))); v1 ^= v0; }
    TF_RND(13) TF_RND(15) TF_RND(26) TF_RND(6)   v0 += k1;  v1 += ks2 + 1u;
    TF_RND(17) TF_RND(29) TF_RND(16) TF_RND(24)  v0 += ks2; v1 += k0 + 2u;
    TF_RND(13) TF_RND(15) TF_RND(26) TF_RND(6)   v0 += k0;  v1 += k1 + 3u;
    TF_RND(17) TF_RND(29) TF_RND(16) TF_RND(24)  v0 += k1;  v1 += ks2 + 4u;
    TF_RND(13) TF_RND(15) TF_RND(26) TF_RND(6)   v0 += ks2; v1 += k0 + 5u;
#undef TF_RND
    o0 = v0; o1 = v1;
}

__global__ void sample_kernel(int layer) {
    int j = blockIdx.x * blockDim.x + threadIdx.x;
    if (j >= LL * UU) return;
    uint32_t a0, a1;
    tf2x32(0u, 42u, 0u, (uint32_t)layer, a0, a1);
    uint32_t k2a, k2b;
    tf2x32(a0, a1, 0u, 1u, k2a, k2b);
    uint32_t o0, o1;
    tf2x32(k2a, k2b, 0u, (uint32_t)j, o0, o1);
    g_samp[j] = (int)((o0 ^ o1) & 2047u);
}

// ---------------- input layernorm over C_IN=32 ----------------
__global__ void ln32_kernel(const float* __restrict__ x,
                            const float* __restrict__ g, const float* __restrict__ b) {
    int row  = blockIdx.x * 8 + (threadIdx.x >> 5);
    int lane = threadIdx.x & 31;
    float v = x[(size_t)row * CIN + lane];
    float s = v;
    #pragma unroll
    for (int o = 16; o; o >>= 1) s += __shfl_xor_sync(~0u, s, o);
    float m = s * (1.f / 32.f);
    float d = v - m;
    float ss = d * d;
    #pragma unroll
    for (int o = 16; o; o >>= 1) ss += __shfl_xor_sync(~0u, ss, o);
    float r = rsqrtf(ss * (1.f / 32.f) + 1e-5f);
    g_xln[(size_t)row * CIN + lane] = d * r * g[lane] + b[lane];
}

// ---------------- token conv + pe table + time proj ----------------
__global__ void embed_kernel(const float* __restrict__ tfeat,
                             const float* __restrict__ Wtok,
                             const float* __restrict__ Wtime,
                             const float* __restrict__ btime) {
    int bl = blockIdx.x;
    int l = bl & (LL - 1);
    int b = bl >> 11;
    __shared__ float xs[96];
    __shared__ float tf[4];
    int tid = threadIdx.x; // 128
    if (tid < 96) {
        int w = tid / 32, c = tid % 32;
        int lsrc = (l - 1 + w + LL) & (LL - 1);
        xs[tid] = g_xln[((size_t)b * LL + lsrc) * CIN + c];
    }
    if (tid < 4) tf[tid] = tfeat[((size_t)b * LL + l) * 4 + tid];
    __syncthreads();
    for (int m = tid; m < DMODEL; m += 128) {
        float acc = btime[m];
        #pragma unroll 8
        for (int wc = 0; wc < 96; wc++) acc += xs[wc] * Wtok[wc * DMODEL + m];
        #pragma unroll
        for (int t = 0; t < 4; t++) acc += tf[t] * Wtime[m * 4 + t];
        float v = acc + g_pe[l * DMODEL + m];
        size_t idx = ((size_t)b * LL + l) * DMODEL + m;
        g_h[idx] = v;
        g_aH[idx] = __float2half_rn(v);
    }
}

// ---------------- M scores (MLP=24 front-batched gathers) ----------------
__global__ void mscore_kernel() {
    int wid  = (blockIdx.x * blockDim.x + threadIdx.x) >> 5;
    int lane = threadIdx.x & 31;
    if (wid >= BB * NH * LL) return;
    int l = wid & (LL - 1);
    int h = (wid >> 11) & (NH - 1);
    int b = wid >> 14;
    const float* qr = g_qkv + ((size_t)b * LL + l) * 1536 + h * 64;
    float q0 = qr[lane * 2], q1 = qr[lane * 2 + 1];
    int idxs[UU];
    #pragma unroll
    for (int s = 0; s < UU; s++) idxs[s] = g_samp[l * UU + s];
    float vv[UU];
    #pragma unroll
    for (int s = 0; s < UU; s++) {
        const float* kr = g_qkv + ((size_t)b * LL + idxs[s]) * 1536 + 512 + h * 64;
        float2 kf = *(const float2*)(kr + lane * 2);
        vv[s] = q0 * kf.x + q1 * kf.y;
    }
    float mx = -INFINITY, sm = 0.f;
    #pragma unroll
    for (int s = 0; s < UU; s++) {
        float v = vv[s];
        #pragma unroll
        for (int o = 16; o; o >>= 1) v += __shfl_xor_sync(~0u, v, o);
        mx = fmaxf(mx, v);
        sm += v;
    }
    if (lane == 0)
        g_M[((size_t)(b * NH + h)) * LL + l] = mx - sm * (1.0f / (float)LL);
}

// ---------------- top-24 per (b,h), JAX tie semantics ----------------
__global__ void topk_kernel() {
    int bh = blockIdx.x;
    int tid = threadIdx.x;   // 256
    __shared__ float sv[LL];
    __shared__ float rv[256];
    __shared__ int   ri[256];
    for (int i = tid; i < LL; i += 256) sv[i] = g_M[(size_t)bh * LL + i];
    __syncthreads();
    for (int t = 0; t < UU; t++) {
        float bvv = -INFINITY; int bi = LL;
        for (int i = tid; i < LL; i += 256) {
            float v = sv[i];
            if (v > bvv || (v == bvv && i < bi)) { bvv = v; bi = i; }
        }
        rv[tid] = bvv; ri[tid] = bi;
        __syncthreads();
        for (int s = 128; s > 0; s >>= 1) {
            if (tid < s) {
                float v2 = rv[tid + s]; int i2 = ri[tid + s];
                if (v2 > rv[tid] || (v2 == rv[tid] && i2 < ri[tid])) { rv[tid] = v2; ri[tid] = i2; }
            }
            __syncthreads();
        }
        if (tid == 0) { g_idxtop[bh * UU + t] = ri[0]; sv[ri[0]] = -INFINITY; }
        __syncthreads();
    }
}

// ---------------- split-K attention phase 1 (lite: only vmean unless L-1 selected)
__global__ __launch_bounds__(256)
void attnpart_kernel(int lite) {    // grid (64, 8), 256 threads
    int bh = blockIdx.x, kt = blockIdx.y;
    int h = bh & 7, b = bh >> 3;
    int tid = threadIdx.x;
    int wid = tid >> 5, lane = tid & 31;
    int d = tid & 63, part = tid >> 6;
    size_t bL = (size_t)b * LL;

    __shared__ float qs[UU * 64];
    __shared__ float sc[UU][257];
    __shared__ float mt_[UU], lt_[UU];
    __shared__ float svs[4][64];
    __shared__ int need;

    if (tid == 0) need = (lite == 0);
    __syncthreads();
    if (lite && tid < UU) {
        if (g_idxtop[bh * UU + tid] == LL - 1) need = 1;
    }
    __syncthreads();

    if (!need) {
        // vmean contribution only
        float vsum = 0.f;
        for (int kk = part; kk < 256; kk += 4)
            vsum += g_qkv[(bL + kt * 256 + kk) * 1536 + 1024 + h * 64 + d];
        svs[part][d] = vsum;
        __syncthreads();
        if (tid < 64)
            g_pvs[(bh * 8 + kt) * HD + tid] =
                svs[0][tid] + svs[1][tid] + svs[2][tid] + svs[3][tid];
        return;
    }

    for (int i = tid; i < UU * 64; i += 256) {
        int u = i >> 6, dd = i & 63;
        qs[i] = g_qkv[(bL + g_idxtop[bh * UU + u]) * 1536 + h * 64 + dd];
    }
    __syncthreads();

    int k = kt * 256 + tid;
    float4 kr[16];
    const float4* kp = (const float4*)(g_qkv + (bL + k) * 1536 + 512 + h * 64);
    #pragma unroll
    for (int i = 0; i < 16; i++) kr[i] = kp[i];
    #pragma unroll 4
    for (int u = 0; u < UU; u++) {
        const float4* qp = (const float4*)(qs + u * 64);
        float s = 0.f;
        #pragma unroll
        for (int i = 0; i < 16; i++) {
            float4 q4 = qp[i];
            s += q4.x * kr[i].x + q4.y * kr[i].y + q4.z * kr[i].z + q4.w * kr[i].w;
        }
        sc[u][tid] = s * 0.125f;
    }
    __syncthreads();

    #pragma unroll
    for (int j = 0; j < 3; j++) {
        int u = wid * 3 + j;
        float tm = -INFINITY;
        #pragma unroll
        for (int i = 0; i < 8; i++) tm = fmaxf(tm, sc[u][lane + 32 * i]);
        #pragma unroll
        for (int o = 16; o; o >>= 1) tm = fmaxf(tm, __shfl_xor_sync(~0u, tm, o));
        if (lane == 0) mt_[u] = tm;
    }
    __syncthreads();

    #pragma unroll 4
    for (int u = 0; u < UU; u++)
        sc[u][tid] = expf(sc[u][tid] - mt_[u]);
    __syncthreads();

    #pragma unroll
    for (int j = 0; j < 3; j++) {
        int u = wid * 3 + j;
        float ts = 0.f;
        #pragma unroll
        for (int i = 0; i < 8; i++) ts += sc[u][lane + 32 * i];
        #pragma unroll
        for (int o = 16; o; o >>= 1) ts += __shfl_xor_sync(~0u, ts, o);
        if (lane == 0) lt_[u] = ts;
    }

    float acc[UU];
    #pragma unroll
    for (int u = 0; u < UU; u++) acc[u] = 0.f;
    float vsum = 0.f;
    for (int kk = part; kk < 256; kk += 4) {
        float v = g_qkv[(bL + kt * 256 + kk) * 1536 + 1024 + h * 64 + d];
        vsum += v;
        #pragma unroll
        for (int u = 0; u < UU; u++) acc[u] += sc[u][kk] * v;
    }
    __syncthreads();

    #pragma unroll 4
    for (int u = 0; u < UU; u++) sc[u][part * 64 + d] = acc[u];
    svs[part][d] = vsum;
    __syncthreads();

    #pragma unroll
    for (int uu = 0; uu < 6; uu++) {
        int u = uu * 4 + part;
        float tot = sc[u][d] + sc[u][64 + d] + sc[u][128 + d] + sc[u][192 + d];
        g_pacc[(((size_t)bh * 8 + kt) * UU + u) * HD + d] = tot;
    }
    if (tid < UU) {
        g_pm[(bh * 8 + kt) * UU + tid] = mt_[tid];
        g_pl[(bh * 8 + kt) * UU + tid] = lt_[tid];
    }
    if (tid < 64)
        g_pvs[(bh * 8 + kt) * HD + tid] =
            svs[0][tid] + svs[1][tid] + svs[2][tid] + svs[3][tid];
}

// ---------------- split-K attention phase 2: deterministic combine ----------------
__global__ void attncomb_kernel() {   // grid 64, 256 threads
    int bh = blockIdx.x;
    int tid = threadIdx.x;
    int d = tid & 63, ug = tid >> 6;
    #pragma unroll
    for (int uu = 0; uu < 6; uu++) {
        int u = uu * 4 + ug;
        float m = -INFINITY;
        #pragma unroll
        for (int kt = 0; kt < 8; kt++)
            m = fmaxf(m, g_pm[(bh * 8 + kt) * UU + u]);
        float denom = 0.f, numer = 0.f;
        #pragma unroll
        for (int kt = 0; kt < 8; kt++) {
            float e = expf(g_pm[(bh * 8 + kt) * UU + u] - m);
            denom += g_pl[(bh * 8 + kt) * UU + u] * e;
            numer += g_pacc[(((size_t)bh * 8 + kt) * UU + u) * HD + d] * e;
        }
        g_upd[((size_t)bh * UU + u) * HD + d] = numer / denom;
    }
    if (tid < 64) {
        float s = 0.f;
        #pragma unroll
        for (int kt = 0; kt < 8; kt++) s += g_pvs[(bh * 8 + kt) * HD + tid];
        g_vmean[bh * HD + tid] = s * (1.0f / (float)LL);
    }
}

// ---------------- broadcast vmean into fp16 attn buffer ----------------
__global__ void fill_kernel() {
    size_t i = (size_t)blockIdx.x * 256 + threadIdx.x;
    size_t e = i * 2;
    int d = (int)(e & 63);
    int h = (int)((e >> 6) & 7);
    int b = (int)(e >> 20);
    float v0 = g_vmean[(b * NH + h) * HD + d];
    float v1 = g_vmean[(b * NH + h) * HD + d + 1];
    *(uint32_t*)(g_aH + e) = packhf(__float2half_rn(v0), __float2half_rn(v1));
}

// ---------------- scatter updated rows (fp16) ----------------
__global__ void scatter_kernel() {
    int bid = blockIdx.x;
    int u = bid % UU;
    int bh = bid / UU;
    int h = bh & (NH - 1), b = bh >> 3;
    int qi = g_idxtop[bh * UU + u];
    float v = g_upd[(size_t)bid * HD + threadIdx.x];
    size_t idx = (((size_t)b * LL + qi) * NH + h) * HD + threadIdx.x;
    g_aH[idx] = __float2half_rn(v);
}

// ---------------- layernorm over 512 (optionally emits fp16) ----------------
__global__ void ln512_kernel(const float* __restrict__ in, float* __restrict__ out,
                             const float* __restrict__ g, const float* __restrict__ b,
                             size_t strideIn, size_t strideOut,
                             __half* __restrict__ hOut) {
    int row = blockIdx.x;
    int tid = threadIdx.x;  // 128
    const float* x = in + (size_t)row * strideIn;
    float4 v = *(const float4*)(x + tid * 4);
    float s  = v.x + v.y + v.z + v.w;
    float ss = v.x*v.x + v.y*v.y + v.z*v.z + v.w*v.w;
    __shared__ float rs[4], rss[4];
    #pragma unroll
    for (int o = 16; o; o >>= 1) {
        s  += __shfl_xor_sync(~0u, s, o);
        ss += __shfl_xor_sync(~0u, ss, o);
    }
    int w = tid >> 5, lane = tid & 31;
    if (lane == 0) { rs[w] = s; rss[w] = ss; }
    __syncthreads();
    s  = rs[0] + rs[1] + rs[2] + rs[3];
    ss = rss[0] + rss[1] + rss[2] + rss[3];
    float m = s * (1.f / 512.f);
    float var = ss * (1.f / 512.f) - m * m;
    float r = rsqrtf(var + 1e-5f);
    float4 gg = *(const float4*)(g + tid * 4);
    float4 bb = *(const float4*)(b + tid * 4);
    float4 o4;
    o4.x = (v.x - m) * r * gg.x + bb.x;
    o4.y = (v.y - m) * r * gg.y + bb.y;
    o4.z = (v.z - m) * r * gg.z + bb.z;
    o4.w = (v.w - m) * r * gg.w + bb.w;
    *(float4*)(out + (size_t)row * strideOut + tid * 4) = o4;
    if (hOut) {
        size_t e = (size_t)row * DMODEL + tid * 4;
        *(uint2*)(hOut + e) = make_uint2(
            packhf(__float2half_rn(o4.x), __float2half_rn(o4.y)),
            packhf(__float2half_rn(o4.z), __float2half_rn(o4.w)));
    }
}

// ---------------- tail: layer-2 post-attention for the LAST row of each batch -----
__global__ __launch_bounds__(512)
void tail_kernel(const float* __restrict__ Wo, const float* __restrict__ bo,
                 const float* __restrict__ W1, const float* __restrict__ b1,
                 const float* __restrict__ W2, const float* __restrict__ b2,
                 const float* __restrict__ g1v, const float* __restrict__ be1v,
                 const float* __restrict__ g2v, const float* __restrict__ be2v,
                 const float* __restrict__ genc, const float* __restrict__ benc,
                 const float* __restrict__ Wpre, const float* __restrict__ bpre,
                 const float* __restrict__ Wfc,  const float* __restrict__ bfc,
                 float* __restrict__ out) {
    int b = blockIdx.x;           // 8
    int tid = threadIdx.x;        // 512
    int wid = tid >> 5, lane = tid & 31;
    __shared__ float av[512];
    __shared__ float hA[512];
    __shared__ float hid[2048];
    __shared__ float rs[16], rss[16];

    {
        int h = tid >> 6, d = tid & 63;
        float v = g_vmean[(b * NH + h) * HD + d];
        #pragma unroll 4
        for (int u = 0; u < UU; u++)
            if (g_idxtop[(b * NH + h) * UU + u] == LL - 1)
                v = g_upd[((size_t)(b * NH + h) * UU + u) * HD + d];
        av[tid] = v;
    }
    __syncthreads();

    float t = bo[tid];
    {
        const float4* wr = (const float4*)(Wo + (size_t)tid * 512);
        const float4* ar = (const float4*)av;
        #pragma unroll 8
        for (int k = 0; k < 128; k++) {
            float4 w4 = wr[k], a4 = ar[k];
            t += a4.x * w4.x + a4.y * w4.y + a4.z * w4.z + a4.w * w4.w;
        }
        t += g_h[((size_t)b * LL + (LL - 1)) * DMODEL + tid];
    }

    {
        float s = t, ss = t * t;
        #pragma unroll
        for (int o = 16; o; o >>= 1) {
            s  += __shfl_xor_sync(~0u, s, o);
            ss += __shfl_xor_sync(~0u, ss, o);
        }
        if (lane == 0) { rs[wid] = s; rss[wid] = ss; }
        __syncthreads();
        float S = 0.f, SS = 0.f;
        #pragma unroll
        for (int w = 0; w < 16; w++) { S += rs[w]; SS += rss[w]; }
        float m = S * (1.f / 512.f);
        float r = rsqrtf(SS * (1.f / 512.f) - m * m + 1e-5f);
        hA[tid] = (t - m) * r * g1v[tid] + be1v[tid];
        __syncthreads();
    }

    #pragma unroll
    for (int jj = 0; jj < 4; jj++) {
        int j = tid + jj * 512;
        float acc = b1[j];
        const float4* wr = (const float4*)(W1 + (size_t)j * 512);
        const float4* ar = (const float4*)hA;
        #pragma unroll 8
        for (int k = 0; k < 128; k++) {
            float4 w4 = wr[k], a4 = ar[k];
            acc += a4.x * w4.x + a4.y * w4.y + a4.z * w4.z + a4.w * w4.w;
        }
        hid[j] = fmaxf(acc, 0.f);
    }
    __syncthreads();

    float t2;
    {
        float acc = b2[tid];
        const float4* wr = (const float4*)(W2 + (size_t)tid * 2048);
        const float4* ar = (const float4*)hid;
        #pragma unroll 8
        for (int k = 0; k < 512; k++) {
            float4 w4 = wr[k], a4 = ar[k];
            acc += a4.x * w4.x + a4.y * w4.y + a4.z * w4.z + a4.w * w4.w;
        }
        t2 = hA[tid] + acc;
    }
    __syncthreads();

    {
        float s = t2, ss = t2 * t2;
        #pragma unroll
        for (int o = 16; o; o >>= 1) {
            s  += __shfl_xor_sync(~0u, s, o);
            ss += __shfl_xor_sync(~0u, ss, o);
        }
        if (lane == 0) { rs[wid] = s; rss[wid] = ss; }
        __syncthreads();
        float S = 0.f, SS = 0.f;
        #pragma unroll
        for (int w = 0; w < 16; w++) { S += rs[w]; SS += rss[w]; }
        float m = S * (1.f / 512.f);
        float r = rsqrtf(SS * (1.f / 512.f) - m * m + 1e-5f);
        float hB = (t2 - m) * r * g2v[tid] + be2v[tid];
        __syncthreads();

        s = hB; ss = hB * hB;
        #pragma unroll
        for (int o = 16; o; o >>= 1) {
            s  += __shfl_xor_sync(~0u, s, o);
            ss += __shfl_xor_sync(~0u, ss, o);
        }
        if (lane == 0) { rs[wid] = s; rss[wid] = ss; }
        __syncthreads();
        S = 0.f; SS = 0.f;
        #pragma unroll
        for (int w = 0; w < 16; w++) { S += rs[w]; SS += rss[w]; }
        m = S * (1.f / 512.f);
        r = rsqrtf(SS * (1.f / 512.f) - m * m + 1e-5f);
        av[tid] = (hB - m) * r * genc[tid] + benc[tid];
        __syncthreads();
    }

    float contrib = 0.f;
    if (tid < 256) {
        float acc = bpre[tid];
        const float4* wr = (const float4*)(Wpre + (size_t)tid * 512);
        const float4* ar = (const float4*)av;
        #pragma unroll 8
        for (int k = 0; k < 128; k++) {
            float4 w4 = wr[k], a4 = ar[k];
            acc += a4.x * w4.x + a4.y * w4.y + a4.z * w4.z + a4.w * w4.w;
        }
        contrib = fmaxf(acc, 0.f) * Wfc[tid];
    }
    {
        float s = contrib;
        #pragma unroll
        for (int o = 16; o; o >>= 1) s += __shfl_xor_sync(~0u, s, o);
        if (lane == 0) rs[wid] = s;
        __syncthreads();
        if (tid == 0) {
            float S = 0.f;
            #pragma unroll
            for (int w = 0; w < 16; w++) S += rs[w];
            out[b] = S + bfc[0];
        }
    }
}

// ---------------- host orchestration ----------------
#define SMEM_GEMM 98304

extern "C" void kernel_launch(void* const* d_in, const int* in_sizes, int n_in,
                              void* d_out, int out_size) {
    const float* x      = (const float*)d_in[0];
    const float* tfeat  = (const float*)d_in[1];
    const float* g_in   = (const float*)d_in[2];
    const float* b_in   = (const float*)d_in[3];
    const float* W_tok  = (const float*)d_in[4];
    const float* W_time = (const float*)d_in[5];
    const float* b_time = (const float*)d_in[6];
    const float* Wq     = (const float*)d_in[7];
    const float* bq     = (const float*)d_in[8];
    const float* Wk     = (const float*)d_in[9];
    const float* bk     = (const float*)d_in[10];
    const float* Wv     = (const float*)d_in[11];
    const float* bv     = (const float*)d_in[12];
    const float* Wo     = (const float*)d_in[13];
    const float* bo     = (const float*)d_in[14];
    const float* W1     = (const float*)d_in[15];
    const float* b1     = (const float*)d_in[16];
    const float* W2     = (const float*)d_in[17];
    const float* b2     = (const float*)d_in[18];
    const float* g1     = (const float*)d_in[19];
    const float* be1    = (const float*)d_in[20];
    const float* g2     = (const float*)d_in[21];
    const float* be2    = (const float*)d_in[22];
    const float* g_enc  = (const float*)d_in[23];
    const float* b_enc  = (const float*)d_in[24];
    const float* W_pre  = (const float*)d_in[25];
    const float* b_pre  = (const float*)d_in[26];
    const float* W_fc   = (const float*)d_in[27];
    const float* b_fc   = (const float*)d_in[28];

    float *h, *qkv;
    __half *aH, *fH, *wbH;
    cudaGetSymbolAddress((void**)&h,   g_h);
    cudaGetSymbolAddress((void**)&qkv, g_qkv);
    cudaGetSymbolAddress((void**)&aH,  g_aH);
    cudaGetSymbolAddress((void**)&fH,  g_fH);
    cudaGetSymbolAddress((void**)&wbH, g_wbH);

    cudaFuncSetAttribute(tgemm_kernel<0,0,0,1>, cudaFuncAttributeMaxDynamicSharedMemorySize, SMEM_GEMM);
    cudaFuncSetAttribute(tgemm_kernel<1,0,1,0>, cudaFuncAttributeMaxDynamicSharedMemorySize, SMEM_GEMM);
    cudaFuncSetAttribute(tgemm_kernel<0,1,0,0>, cudaFuncAttributeMaxDynamicSharedMemorySize, SMEM_GEMM);

    pe_kernel<<<256, 256>>>();
    ln32_kernel<<<MROWS / 8, 256>>>(x, g_in, b_in);
    embed_kernel<<<MROWS, 128>>>(tfeat, W_tok, W_time, b_time);
    wconv_kernel<<<WTOT_F4 / 256, 256>>>((const float4*)Wq, (const float4*)Wk,
                                         (const float4*)Wv, (const float4*)Wo,
                                         (const float4*)W1, (const float4*)W2);

    dim3 gQKV(1536 / 128, MROWS / 128);
    dim3 gO(DMODEL / 128, MROWS / 128);
    dim3 gF1(DFF / 128,  MROWS / 128);
    dim3 gF2(DMODEL / 128, MROWS / 128);

    for (int i = 0; i < NE; i++) {
        size_t bOff  = (size_t)i * DMODEL;
        size_t b1Off = (size_t)i * DFF;
        size_t qkvW  = (size_t)i * QKV_PER_LAYER;
        size_t woW   = WO_OFF + (size_t)i * DMODEL * DMODEL;
        size_t w1W   = W1_OFF + (size_t)i * DFF * DMODEL;
        size_t w2W   = W2_OFF + (size_t)i * DFF * DMODEL;

        sample_kernel<<<(LL * UU + 255) / 256, 256>>>(i);

        tgemm_kernel<0,0,0,1><<<gQKV, 256, SMEM_GEMM>>>(
            aH, wbH + qkvW,
            bq + bOff, bk + bOff, bv + bOff, nullptr, qkv, nullptr,
            MROWS, 1536, DMODEL);

        mscore_kernel<<<(BB * NH * LL * 32) / 256, 256>>>();
        topk_kernel<<<BB * NH, 256>>>();
        attnpart_kernel<<<dim3(BB * NH, 8), 256>>>(i);
        attncomb_kernel<<<BB * NH, 256>>>();

        if (i == 0) {
            fill_kernel<<<(MROWS * DMODEL / 2) / 256, 256>>>();
            scatter_kernel<<<BB * NH * UU, HD>>>();

            tgemm_kernel<0,1,0,0><<<gO, 256, SMEM_GEMM>>>(
                aH, wbH + woW,
                bo + bOff, nullptr, nullptr, h, h, nullptr,
                MROWS, DMODEL, DMODEL);
            ln512_kernel<<<MROWS, 128>>>(h, h, g1 + bOff, be1 + bOff, DMODEL, DMODEL, aH);

            tgemm_kernel<1,0,1,0><<<gF1, 256, SMEM_GEMM>>>(
                aH, wbH + w1W,
                b1 + b1Off, nullptr, nullptr, nullptr, nullptr, fH,
                MROWS, DFF, DMODEL);
            tgemm_kernel<0,1,0,0><<<gF2, 256, SMEM_GEMM>>>(
                fH, wbH + w2W,
                b2 + bOff, nullptr, nullptr, h, h, nullptr,
                MROWS, DMODEL, DFF);
            ln512_kernel<<<MROWS, 128>>>(h, h, g2 + bOff, be2 + bOff, DMODEL, DMODEL, aH);
        } else {
            // layer 2: only row L-1 per batch reaches the output -> fp32 tail
            tail_kernel<<<BB, 512>>>(
                Wo + (size_t)i * DMODEL * DMODEL, bo + bOff,
                W1 + (size_t)i * DFF * DMODEL, b1 + b1Off,
                W2 + (size_t)i * DMODEL * DFF, b2 + bOff,
                g1 + bOff, be1 + bOff, g2 + bOff, be2 + bOff,
                g_enc, b_enc, W_pre, b_pre, W_fc, b_fc, (float*)d_out);
        }
    }
}